// round 1
// baseline (speedup 1.0000x reference)
#include <cuda_runtime.h>
#include <math.h>

#define BB 2
#define TT 2048
#define HH 1024
#define NH 16
#define HD 64
#define MAXREL 4

// Scratch (static device globals — no allocation in kernel_launch)
__device__ float g_Q[BB*TT*HH];
__device__ float g_K[BB*TT*HH];
__device__ float g_V[BB*TT*HH];
__device__ float g_Hid[BB*TT*HH];

// ---------------------------------------------------------------------------
// GEMM: C[M,N] = A[M,K] @ W[N,K]^T + bias[N], optional per-row int mask mult.
// 128x128 tile, K-step 8, 256 threads, 8x8 micro-tile.
// ---------------------------------------------------------------------------
__global__ __launch_bounds__(256) void gemm_bias_kernel(
    const float* __restrict__ A, const float* __restrict__ W,
    const float* __restrict__ bias, float* __restrict__ C,
    const int* __restrict__ mask, int M, int N, int K)
{
    __shared__ float As[8][132];
    __shared__ float Bs[8][132];
    const int tid = threadIdx.x;
    const int tx = tid & 15;
    const int ty = tid >> 4;
    const int mbase = blockIdx.y * 128;
    const int nbase = blockIdx.x * 128;
    const int lr = tid >> 1;          // 0..127
    const int lk = (tid & 1) << 2;    // 0 or 4

    const float* Ap = A + (size_t)(mbase + lr) * K + lk;
    const float* Wp = W + (size_t)(nbase + lr) * K + lk;

    float acc[8][8];
    #pragma unroll
    for (int i = 0; i < 8; i++)
        #pragma unroll
        for (int j = 0; j < 8; j++) acc[i][j] = 0.f;

    for (int kk = 0; kk < K; kk += 8) {
        float4 av = *(const float4*)(Ap + kk);
        float4 wv = *(const float4*)(Wp + kk);
        As[lk+0][lr] = av.x; As[lk+1][lr] = av.y; As[lk+2][lr] = av.z; As[lk+3][lr] = av.w;
        Bs[lk+0][lr] = wv.x; Bs[lk+1][lr] = wv.y; Bs[lk+2][lr] = wv.z; Bs[lk+3][lr] = wv.w;
        __syncthreads();
        #pragma unroll
        for (int k = 0; k < 8; k++) {
            float a[8], b[8];
            #pragma unroll
            for (int i = 0; i < 8; i++) a[i] = As[k][ty*8+i];
            #pragma unroll
            for (int j = 0; j < 8; j++) b[j] = Bs[k][tx*8+j];
            #pragma unroll
            for (int i = 0; i < 8; i++)
                #pragma unroll
                for (int j = 0; j < 8; j++)
                    acc[i][j] = fmaf(a[i], b[j], acc[i][j]);
        }
        __syncthreads();
    }

    #pragma unroll
    for (int i = 0; i < 8; i++) {
        int row = mbase + ty*8 + i;
        float mv = mask ? (float)mask[row] : 1.f;
        float4 r0, r1;
        r0.x = (acc[i][0] + bias[nbase + tx*8 + 0]) * mv;
        r0.y = (acc[i][1] + bias[nbase + tx*8 + 1]) * mv;
        r0.z = (acc[i][2] + bias[nbase + tx*8 + 2]) * mv;
        r0.w = (acc[i][3] + bias[nbase + tx*8 + 3]) * mv;
        r1.x = (acc[i][4] + bias[nbase + tx*8 + 4]) * mv;
        r1.y = (acc[i][5] + bias[nbase + tx*8 + 5]) * mv;
        r1.z = (acc[i][6] + bias[nbase + tx*8 + 6]) * mv;
        r1.w = (acc[i][7] + bias[nbase + tx*8 + 7]) * mv;
        *(float4*)&C[(size_t)row*N + nbase + tx*8 + 0] = r0;
        *(float4*)&C[(size_t)row*N + nbase + tx*8 + 4] = r1;
    }
}

// ---------------------------------------------------------------------------
// Flash attention with clipped relative bias + key mask.
// Block = (b, head, 64-query tile). 256 threads. BK = 64.
// ---------------------------------------------------------------------------
#define BQ 64
#define BK 64
#define SP 68   // padded SMEM row stride (floats)

#define ATTN_SMEM ((BQ*SP + HD*SP + BK*SP + BQ*SP) * 4)

__global__ __launch_bounds__(256) void attn_kernel(
    const float* __restrict__ Q, const float* __restrict__ Kg,
    const float* __restrict__ V, const int* __restrict__ mask,
    const float* __restrict__ rel_bias, float* __restrict__ Out)
{
    extern __shared__ float sm[];
    float* Qs = sm;                // [BQ][SP]  q-major, d inner
    float* Kt = Qs + BQ*SP;        // [HD][SP]  d-major, key inner (transposed)
    float* Vs = Kt + HD*SP;        // [BK][SP]  key-major, d inner
    float* S  = Vs + BK*SP;        // [BQ][SP]
    __shared__ float m_i[BQ], l_i[BQ], alpha_s[BQ];
    __shared__ float biasv[2*MAXREL+1];
    __shared__ int   maskv[BK];

    const int tid = threadIdx.x;
    const int tx = tid & 15;
    const int ty = tid >> 4;
    const int b  = blockIdx.z;
    const int h  = blockIdx.y;
    const int q0 = blockIdx.x * BQ;
    const float scale = 0.125f;   // 64^-0.5

    // Load Q tile (64x64): thread -> (row = tid&63, d0 = (tid>>6)*16)
    {
        int r  = tid & 63;
        int d0 = (tid >> 6) * 16;
        const float* src = Q + (size_t)(b*TT + q0 + r)*HH + h*HD + d0;
        float* dst = Qs + r*SP + d0;
        #pragma unroll
        for (int i = 0; i < 4; i++)
            *(float4*)(dst + i*4) = *(const float4*)(src + i*4);
    }
    if (tid < 2*MAXREL+1) biasv[tid] = rel_bias[tid*NH + h];
    if (tid < BQ) { m_i[tid] = -INFINITY; l_i[tid] = 0.f; }

    float o[4][4];
    #pragma unroll
    for (int i = 0; i < 4; i++)
        #pragma unroll
        for (int j = 0; j < 4; j++) o[i][j] = 0.f;

    for (int kt = 0; kt < TT/BK; kt++) {
        const int k0 = kt * BK;
        __syncthreads();  // prior iteration's PV reads of Vs/S complete (also covers Qs/init on iter 0)

        // Load K (transposed to d-major) and V (natural), plus key mask
        {
            int r  = tid & 63;
            int d0 = (tid >> 6) * 16;
            const float* ksrc = Kg + (size_t)(b*TT + k0 + r)*HH + h*HD + d0;
            const float* vsrc = V  + (size_t)(b*TT + k0 + r)*HH + h*HD + d0;
            #pragma unroll
            for (int i = 0; i < 4; i++) {
                float4 kv = *(const float4*)(ksrc + i*4);
                float4 vv = *(const float4*)(vsrc + i*4);
                int d = d0 + i*4;
                Kt[(d+0)*SP + r] = kv.x;
                Kt[(d+1)*SP + r] = kv.y;
                Kt[(d+2)*SP + r] = kv.z;
                Kt[(d+3)*SP + r] = kv.w;
                *(float4*)(Vs + r*SP + d) = vv;
            }
            if (tid < BK) maskv[tid] = mask[b*TT + k0 + tid];
        }
        __syncthreads();

        // S = Q @ K^T : each thread computes a 4x4 micro-tile
        float s[4][4];
        #pragma unroll
        for (int i = 0; i < 4; i++)
            #pragma unroll
            for (int j = 0; j < 4; j++) s[i][j] = 0.f;

        #pragma unroll 8
        for (int d = 0; d < HD; d++) {
            float a0 = Qs[(ty*4+0)*SP + d];
            float a1 = Qs[(ty*4+1)*SP + d];
            float a2 = Qs[(ty*4+2)*SP + d];
            float a3 = Qs[(ty*4+3)*SP + d];
            float4 bv = *(const float4*)(Kt + d*SP + tx*4);
            s[0][0] = fmaf(a0, bv.x, s[0][0]); s[0][1] = fmaf(a0, bv.y, s[0][1]);
            s[0][2] = fmaf(a0, bv.z, s[0][2]); s[0][3] = fmaf(a0, bv.w, s[0][3]);
            s[1][0] = fmaf(a1, bv.x, s[1][0]); s[1][1] = fmaf(a1, bv.y, s[1][1]);
            s[1][2] = fmaf(a1, bv.z, s[1][2]); s[1][3] = fmaf(a1, bv.w, s[1][3]);
            s[2][0] = fmaf(a2, bv.x, s[2][0]); s[2][1] = fmaf(a2, bv.y, s[2][1]);
            s[2][2] = fmaf(a2, bv.z, s[2][2]); s[2][3] = fmaf(a2, bv.w, s[2][3]);
            s[3][0] = fmaf(a3, bv.x, s[3][0]); s[3][1] = fmaf(a3, bv.y, s[3][1]);
            s[3][2] = fmaf(a3, bv.z, s[3][2]); s[3][3] = fmaf(a3, bv.w, s[3][3]);
        }

        // scale + relative bias + key mask, write to S
        #pragma unroll
        for (int i = 0; i < 4; i++) {
            int qi = q0 + ty*4 + i;
            #pragma unroll
            for (int j = 0; j < 4; j++) {
                int kj = k0 + tx*4 + j;
                int rel = kj - qi;
                rel = min(max(rel, -MAXREL), MAXREL) + MAXREL;
                float val = s[i][j]*scale + biasv[rel];
                if (!maskv[tx*4+j]) val = -10000.f;
                S[(ty*4+i)*SP + tx*4 + j] = val;
            }
        }
        __syncthreads();

        // Online softmax: warp w handles rows [w*8, w*8+8)
        {
            int wid  = tid >> 5;
            int lane = tid & 31;
            #pragma unroll
            for (int rr = 0; rr < 8; rr++) {
                int row = wid*8 + rr;
                float v0 = S[row*SP + lane];
                float v1 = S[row*SP + lane + 32];
                float mx = fmaxf(v0, v1);
                #pragma unroll
                for (int off = 16; off > 0; off >>= 1)
                    mx = fmaxf(mx, __shfl_xor_sync(0xffffffffu, mx, off));
                float mold = m_i[row];
                float mnew = fmaxf(mold, mx);
                float p0 = __expf(v0 - mnew);
                float p1 = __expf(v1 - mnew);
                S[row*SP + lane]      = p0;
                S[row*SP + lane + 32] = p1;
                float sum = p0 + p1;
                #pragma unroll
                for (int off = 16; off > 0; off >>= 1)
                    sum += __shfl_xor_sync(0xffffffffu, sum, off);
                __syncwarp();
                if (lane == 0) {
                    float al = __expf(mold - mnew);   // mold=-inf -> 0
                    l_i[row] = l_i[row]*al + sum;
                    m_i[row] = mnew;
                    alpha_s[row] = al;
                }
                __syncwarp();
            }
        }
        __syncthreads();

        // Rescale O and accumulate P @ V
        float al0 = alpha_s[ty*4+0];
        float al1 = alpha_s[ty*4+1];
        float al2 = alpha_s[ty*4+2];
        float al3 = alpha_s[ty*4+3];
        #pragma unroll
        for (int j = 0; j < 4; j++) {
            o[0][j] *= al0; o[1][j] *= al1; o[2][j] *= al2; o[3][j] *= al3;
        }
        #pragma unroll 8
        for (int k = 0; k < BK; k++) {
            float p0 = S[(ty*4+0)*SP + k];
            float p1 = S[(ty*4+1)*SP + k];
            float p2 = S[(ty*4+2)*SP + k];
            float p3 = S[(ty*4+3)*SP + k];
            float4 vv = *(const float4*)(Vs + k*SP + tx*4);
            o[0][0] = fmaf(p0, vv.x, o[0][0]); o[0][1] = fmaf(p0, vv.y, o[0][1]);
            o[0][2] = fmaf(p0, vv.z, o[0][2]); o[0][3] = fmaf(p0, vv.w, o[0][3]);
            o[1][0] = fmaf(p1, vv.x, o[1][0]); o[1][1] = fmaf(p1, vv.y, o[1][1]);
            o[1][2] = fmaf(p1, vv.z, o[1][2]); o[1][3] = fmaf(p1, vv.w, o[1][3]);
            o[2][0] = fmaf(p2, vv.x, o[2][0]); o[2][1] = fmaf(p2, vv.y, o[2][1]);
            o[2][2] = fmaf(p2, vv.z, o[2][2]); o[2][3] = fmaf(p2, vv.w, o[2][3]);
            o[3][0] = fmaf(p3, vv.x, o[3][0]); o[3][1] = fmaf(p3, vv.y, o[3][1]);
            o[3][2] = fmaf(p3, vv.z, o[3][2]); o[3][3] = fmaf(p3, vv.w, o[3][3]);
        }
    }

    // Epilogue: divide by l, write to hidden in [B,T,H] layout
    #pragma unroll
    for (int i = 0; i < 4; i++) {
        int row = ty*4 + i;
        float linv = 1.f / l_i[row];
        float4 r;
        r.x = o[i][0]*linv; r.y = o[i][1]*linv;
        r.z = o[i][2]*linv; r.w = o[i][3]*linv;
        *(float4*)&Out[(size_t)(b*TT + q0 + row)*HH + h*HD + tx*4] = r;
    }
}

// ---------------------------------------------------------------------------
extern "C" void kernel_launch(void* const* d_in, const int* in_sizes, int n_in,
                              void* d_out, int out_size)
{
    const float* x         = (const float*)d_in[0];
    const int*   text_mask = (const int*)  d_in[1];
    const float* Wq        = (const float*)d_in[2];
    const float* bq        = (const float*)d_in[3];
    const float* Wk        = (const float*)d_in[4];
    const float* bk        = (const float*)d_in[5];
    const float* Wv        = (const float*)d_in[6];
    const float* bv        = (const float*)d_in[7];
    const float* Wo        = (const float*)d_in[8];
    const float* bo        = (const float*)d_in[9];
    const float* rel_bias  = (const float*)d_in[10];
    float* out = (float*)d_out;

    float *Qp, *Kp, *Vp, *Hp;
    cudaGetSymbolAddress((void**)&Qp, g_Q);
    cudaGetSymbolAddress((void**)&Kp, g_K);
    cudaGetSymbolAddress((void**)&Vp, g_V);
    cudaGetSymbolAddress((void**)&Hp, g_Hid);

    const int M = BB * TT;
    dim3 gdim(HH/128, M/128);

    gemm_bias_kernel<<<gdim, 256>>>(x, Wq, bq, Qp, nullptr, M, HH, HH);
    gemm_bias_kernel<<<gdim, 256>>>(x, Wk, bk, Kp, nullptr, M, HH, HH);
    gemm_bias_kernel<<<gdim, 256>>>(x, Wv, bv, Vp, nullptr, M, HH, HH);

    cudaFuncSetAttribute(attn_kernel, cudaFuncAttributeMaxDynamicSharedMemorySize, ATTN_SMEM);
    attn_kernel<<<dim3(TT/BQ, NH, BB), 256, ATTN_SMEM>>>(Qp, Kp, Vp, text_mask, rel_bias, Hp);

    gemm_bias_kernel<<<gdim, 256>>>(Hp, Wo, bo, out, text_mask, M, HH, HH);
}

// round 3
// speedup vs baseline: 1.3221x; 1.3221x over previous
#include <cuda_runtime.h>
#include <cuda_bf16.h>
#include <math.h>
#include <stdint.h>

#define BB 2
#define TT 2048
#define HH 1024
#define NH 16
#define HD 64
#define MAXREL 4

// Scratch (static device globals — no allocation in kernel_launch)
__device__ float g_Q[BB*TT*HH];
__device__ float g_K[BB*TT*HH];
__device__ float g_V[BB*TT*HH];
__device__ float g_Hid[BB*TT*HH];

// ===========================================================================
// Helpers (portable PTX only — nothing arch-'a'-gated)
// ===========================================================================
__device__ __forceinline__ uint32_t smem_u32(const void* p) {
    uint32_t a;
    asm("{ .reg .u64 t; cvta.to.shared.u64 t, %1; cvt.u32.u64 %0, t; }" : "=r"(a) : "l"(p));
    return a;
}
__device__ __forceinline__ void ldsm_x4(uint32_t& r0, uint32_t& r1, uint32_t& r2, uint32_t& r3,
                                        uint32_t addr) {
    asm volatile("ldmatrix.sync.aligned.m8n8.x4.shared.b16 {%0,%1,%2,%3}, [%4];"
                 : "=r"(r0), "=r"(r1), "=r"(r2), "=r"(r3) : "r"(addr));
}
__device__ __forceinline__ void mma16816(float* c, const uint32_t* a, uint32_t b0, uint32_t b1) {
    asm volatile(
        "mma.sync.aligned.m16n8k16.row.col.f32.bf16.bf16.f32 "
        "{%0,%1,%2,%3}, {%4,%5,%6,%7}, {%8,%9}, {%0,%1,%2,%3};"
        : "+f"(c[0]), "+f"(c[1]), "+f"(c[2]), "+f"(c[3])
        : "r"(a[0]), "r"(a[1]), "r"(a[2]), "r"(a[3]), "r"(b0), "r"(b1));
}
// bf16 hi/lo split pack: hi = {bf16(x) low-half, bf16(y) high-half}, lo = residuals
__device__ __forceinline__ void split2(float x, float y, uint32_t& hi, uint32_t& lo) {
    float hx = __bfloat162float(__float2bfloat16(x));
    float hy = __bfloat162float(__float2bfloat16(y));
    asm("cvt.rn.bf16x2.f32 %0, %1, %2;" : "=r"(hi) : "f"(hy), "f"(hx));
    asm("cvt.rn.bf16x2.f32 %0, %1, %2;" : "=r"(lo) : "f"(y - hy), "f"(x - hx));
}

// ===========================================================================
// mma.sync GEMM: C[M,N] = A[M,K=1024] @ W[N,K=1024]^T + bias[N], opt row mask.
// CTA 128x128, 256 thr (8 warps, 4m x 2n), warp tile 32x64, K-chunk 32.
// bf16 hi/lo x3 MMA -> fp32-accurate. Double-buffered SMEM, 80B row stride.
// ===========================================================================
#define GK 1024
#define KC 32
#define NCHUNK (GK / KC)
#define ROWB 80                 // bytes per SMEM row (32 bf16 data + pad)
#define TILEB (128 * ROWB)      // 10240 B per precision tile
#define BUFB (4 * TILEB)        // Ahi|Alo|Bhi|Blo
#define GEMM_SMEM (2 * BUFB)    // 81920 B

__global__ __launch_bounds__(256) void gemm_mma_kernel(
    const float* __restrict__ A, const float* __restrict__ W,
    const float* __restrict__ bias, float* __restrict__ C,
    const int* __restrict__ mask, int N)
{
    extern __shared__ char smemraw[];
    uint32_t* sm32 = (uint32_t*)smemraw;
    const uint32_t sbase = smem_u32(smemraw);

    const int tid  = threadIdx.x;
    const int lane = tid & 31;
    const int wid  = tid >> 5;
    const int wm   = wid & 3;          // m-block 0..3 (32 rows each)
    const int wn   = wid >> 2;         // n-block 0..1 (64 cols each)
    const int mbase = blockIdx.y * 128;
    const int nbase = blockIdx.x * 128;

    // global load mapping: thread -> (row = tid>>1, 16-float half = tid&1)
    const int lr   = tid >> 1;
    const int half = tid & 1;
    const float* Ap = A + (size_t)(mbase + lr) * GK + half * 16;
    const float* Wp = W + (size_t)(nbase + lr) * GK + half * 16;
    const int rowoff = lr * (ROWB/4) + half * 8;     // uint32 index within a tile

    float acc[2][8][4];
    #pragma unroll
    for (int mi = 0; mi < 2; mi++)
        #pragma unroll
        for (int j = 0; j < 8; j++)
            #pragma unroll
            for (int e = 0; e < 4; e++) acc[mi][j][e] = 0.f;

    float4 av[4], wv[4];   // staged global data for next chunk

    // ldmatrix base addresses (byte offsets added per use)
    // A frag (m16k16): lane -> row (lane&15), k-group (lane>>4)
    const uint32_t aA = sbase + (uint32_t)(wm*32 + (lane & 15)) * ROWB + ((lane >> 4) * 16);
    // B frag pair (two n8 tiles): lane -> n row, k-group
    const uint32_t aB = sbase + 2*TILEB
                      + (uint32_t)(wn*64 + ((lane >> 4) << 3) + (lane & 7)) * ROWB
                      + (((lane >> 3) & 1) * 16);

    // ---- prologue: stage + store chunk 0
    #pragma unroll
    for (int i = 0; i < 4; i++) {
        av[i] = *(const float4*)(Ap + i*4);
        wv[i] = *(const float4*)(Wp + i*4);
    }
    {
        uint32_t hi[8], lo[8];
        #pragma unroll
        for (int i = 0; i < 4; i++) { split2(av[i].x, av[i].y, hi[2*i], lo[2*i]);
                                      split2(av[i].z, av[i].w, hi[2*i+1], lo[2*i+1]); }
        *(uint4*)&sm32[rowoff]                = make_uint4(hi[0],hi[1],hi[2],hi[3]);
        *(uint4*)&sm32[rowoff + 4]            = make_uint4(hi[4],hi[5],hi[6],hi[7]);
        *(uint4*)&sm32[TILEB/4 + rowoff]      = make_uint4(lo[0],lo[1],lo[2],lo[3]);
        *(uint4*)&sm32[TILEB/4 + rowoff + 4]  = make_uint4(lo[4],lo[5],lo[6],lo[7]);
        #pragma unroll
        for (int i = 0; i < 4; i++) { split2(wv[i].x, wv[i].y, hi[2*i], lo[2*i]);
                                      split2(wv[i].z, wv[i].w, hi[2*i+1], lo[2*i+1]); }
        *(uint4*)&sm32[2*TILEB/4 + rowoff]    = make_uint4(hi[0],hi[1],hi[2],hi[3]);
        *(uint4*)&sm32[2*TILEB/4 + rowoff+4]  = make_uint4(hi[4],hi[5],hi[6],hi[7]);
        *(uint4*)&sm32[3*TILEB/4 + rowoff]    = make_uint4(lo[0],lo[1],lo[2],lo[3]);
        *(uint4*)&sm32[3*TILEB/4 + rowoff+4]  = make_uint4(lo[4],lo[5],lo[6],lo[7]);
    }
    __syncthreads();

    for (int c = 0; c < NCHUNK; c++) {
        // stage next chunk (overlaps with MMA below)
        if (c + 1 < NCHUNK) {
            const float* ap = Ap + (c+1) * KC;
            const float* wp = Wp + (c+1) * KC;
            #pragma unroll
            for (int i = 0; i < 4; i++) { av[i] = *(const float4*)(ap + i*4);
                                          wv[i] = *(const float4*)(wp + i*4); }
        }

        // ---- compute on buffer c&1
        const uint32_t boff = (uint32_t)(c & 1) * BUFB;
        #pragma unroll
        for (int ks = 0; ks < 2; ks++) {
            uint32_t Ah[2][4], Al[2][4];
            ldsm_x4(Ah[0][0],Ah[0][1],Ah[0][2],Ah[0][3], aA + boff + ks*32);
            ldsm_x4(Ah[1][0],Ah[1][1],Ah[1][2],Ah[1][3], aA + boff + 16*ROWB + ks*32);
            ldsm_x4(Al[0][0],Al[0][1],Al[0][2],Al[0][3], aA + boff + TILEB + ks*32);
            ldsm_x4(Al[1][0],Al[1][1],Al[1][2],Al[1][3], aA + boff + TILEB + 16*ROWB + ks*32);
            #pragma unroll
            for (int jp = 0; jp < 4; jp++) {
                uint32_t Bh[4], Bl[4];
                ldsm_x4(Bh[0],Bh[1],Bh[2],Bh[3], aB + boff + jp*16*ROWB + ks*32);
                ldsm_x4(Bl[0],Bl[1],Bl[2],Bl[3], aB + boff + TILEB + jp*16*ROWB + ks*32);
                #pragma unroll
                for (int mi = 0; mi < 2; mi++) {
                    mma16816(acc[mi][2*jp],   Ah[mi], Bh[0], Bh[1]);
                    mma16816(acc[mi][2*jp],   Ah[mi], Bl[0], Bl[1]);
                    mma16816(acc[mi][2*jp],   Al[mi], Bh[0], Bh[1]);
                    mma16816(acc[mi][2*jp+1], Ah[mi], Bh[2], Bh[3]);
                    mma16816(acc[mi][2*jp+1], Ah[mi], Bl[2], Bl[3]);
                    mma16816(acc[mi][2*jp+1], Al[mi], Bh[2], Bh[3]);
                }
            }
        }

        // ---- store staged chunk into the other buffer
        if (c + 1 < NCHUNK) {
            const uint32_t sb = (uint32_t)((c+1) & 1) * (BUFB/4);
            uint32_t hi[8], lo[8];
            #pragma unroll
            for (int i = 0; i < 4; i++) { split2(av[i].x, av[i].y, hi[2*i], lo[2*i]);
                                          split2(av[i].z, av[i].w, hi[2*i+1], lo[2*i+1]); }
            *(uint4*)&sm32[sb + rowoff]               = make_uint4(hi[0],hi[1],hi[2],hi[3]);
            *(uint4*)&sm32[sb + rowoff + 4]           = make_uint4(hi[4],hi[5],hi[6],hi[7]);
            *(uint4*)&sm32[sb + TILEB/4 + rowoff]     = make_uint4(lo[0],lo[1],lo[2],lo[3]);
            *(uint4*)&sm32[sb + TILEB/4 + rowoff + 4] = make_uint4(lo[4],lo[5],lo[6],lo[7]);
            #pragma unroll
            for (int i = 0; i < 4; i++) { split2(wv[i].x, wv[i].y, hi[2*i], lo[2*i]);
                                          split2(wv[i].z, wv[i].w, hi[2*i+1], lo[2*i+1]); }
            *(uint4*)&sm32[sb + 2*TILEB/4 + rowoff]   = make_uint4(hi[0],hi[1],hi[2],hi[3]);
            *(uint4*)&sm32[sb + 2*TILEB/4 + rowoff+4] = make_uint4(hi[4],hi[5],hi[6],hi[7]);
            *(uint4*)&sm32[sb + 3*TILEB/4 + rowoff]   = make_uint4(lo[0],lo[1],lo[2],lo[3]);
            *(uint4*)&sm32[sb + 3*TILEB/4 + rowoff+4] = make_uint4(lo[4],lo[5],lo[6],lo[7]);
        }
        __syncthreads();
    }

    // ---- epilogue: bias + optional per-row mask, float2 stores
    #pragma unroll
    for (int mi = 0; mi < 2; mi++) {
        const int r0 = mbase + wm*32 + mi*16 + (lane >> 2);
        const float mv0 = mask ? (float)mask[r0]     : 1.f;
        const float mv1 = mask ? (float)mask[r0 + 8] : 1.f;
        #pragma unroll
        for (int j = 0; j < 8; j++) {
            const int col = nbase + wn*64 + j*8 + (lane & 3)*2;
            const float b0 = bias[col], b1 = bias[col+1];
            float2 o0 = make_float2((acc[mi][j][0] + b0) * mv0, (acc[mi][j][1] + b1) * mv0);
            float2 o1 = make_float2((acc[mi][j][2] + b0) * mv1, (acc[mi][j][3] + b1) * mv1);
            *(float2*)&C[(size_t)r0 * N + col]       = o0;
            *(float2*)&C[(size_t)(r0+8) * N + col]   = o1;
        }
    }
}

// ---------------------------------------------------------------------------
// Flash attention with clipped relative bias + key mask (proven R1 version).
// ---------------------------------------------------------------------------
#define BQ 64
#define BK 64
#define SP 68

#define ATTN_SMEM ((BQ*SP + HD*SP + BK*SP + BQ*SP) * 4)

__global__ __launch_bounds__(256) void attn_kernel(
    const float* __restrict__ Q, const float* __restrict__ Kg,
    const float* __restrict__ V, const int* __restrict__ mask,
    const float* __restrict__ rel_bias, float* __restrict__ Out)
{
    extern __shared__ float sm[];
    float* Qs = sm;
    float* Kt = Qs + BQ*SP;
    float* Vs = Kt + HD*SP;
    float* S  = Vs + BK*SP;
    __shared__ float m_i[BQ], l_i[BQ], alpha_s[BQ];
    __shared__ float biasv[2*MAXREL+1];
    __shared__ int   maskv[BK];

    const int tid = threadIdx.x;
    const int tx = tid & 15;
    const int ty = tid >> 4;
    const int b  = blockIdx.z;
    const int h  = blockIdx.y;
    const int q0 = blockIdx.x * BQ;
    const float scale = 0.125f;

    {
        int r  = tid & 63;
        int d0 = (tid >> 6) * 16;
        const float* src = Q + (size_t)(b*TT + q0 + r)*HH + h*HD + d0;
        float* dst = Qs + r*SP + d0;
        #pragma unroll
        for (int i = 0; i < 4; i++)
            *(float4*)(dst + i*4) = *(const float4*)(src + i*4);
    }
    if (tid < 2*MAXREL+1) biasv[tid] = rel_bias[tid*NH + h];
    if (tid < BQ) { m_i[tid] = -INFINITY; l_i[tid] = 0.f; }

    float o[4][4];
    #pragma unroll
    for (int i = 0; i < 4; i++)
        #pragma unroll
        for (int j = 0; j < 4; j++) o[i][j] = 0.f;

    for (int kt = 0; kt < TT/BK; kt++) {
        const int k0 = kt * BK;
        __syncthreads();

        {
            int r  = tid & 63;
            int d0 = (tid >> 6) * 16;
            const float* ksrc = Kg + (size_t)(b*TT + k0 + r)*HH + h*HD + d0;
            const float* vsrc = V  + (size_t)(b*TT + k0 + r)*HH + h*HD + d0;
            #pragma unroll
            for (int i = 0; i < 4; i++) {
                float4 kv = *(const float4*)(ksrc + i*4);
                float4 vv = *(const float4*)(vsrc + i*4);
                int d = d0 + i*4;
                Kt[(d+0)*SP + r] = kv.x;
                Kt[(d+1)*SP + r] = kv.y;
                Kt[(d+2)*SP + r] = kv.z;
                Kt[(d+3)*SP + r] = kv.w;
                *(float4*)(Vs + r*SP + d) = vv;
            }
            if (tid < BK) maskv[tid] = mask[b*TT + k0 + tid];
        }
        __syncthreads();

        float s[4][4];
        #pragma unroll
        for (int i = 0; i < 4; i++)
            #pragma unroll
            for (int j = 0; j < 4; j++) s[i][j] = 0.f;

        #pragma unroll 8
        for (int d = 0; d < HD; d++) {
            float a0 = Qs[(ty*4+0)*SP + d];
            float a1 = Qs[(ty*4+1)*SP + d];
            float a2 = Qs[(ty*4+2)*SP + d];
            float a3 = Qs[(ty*4+3)*SP + d];
            float4 bv = *(const float4*)(Kt + d*SP + tx*4);
            s[0][0] = fmaf(a0, bv.x, s[0][0]); s[0][1] = fmaf(a0, bv.y, s[0][1]);
            s[0][2] = fmaf(a0, bv.z, s[0][2]); s[0][3] = fmaf(a0, bv.w, s[0][3]);
            s[1][0] = fmaf(a1, bv.x, s[1][0]); s[1][1] = fmaf(a1, bv.y, s[1][1]);
            s[1][2] = fmaf(a1, bv.z, s[1][2]); s[1][3] = fmaf(a1, bv.w, s[1][3]);
            s[2][0] = fmaf(a2, bv.x, s[2][0]); s[2][1] = fmaf(a2, bv.y, s[2][1]);
            s[2][2] = fmaf(a2, bv.z, s[2][2]); s[2][3] = fmaf(a2, bv.w, s[2][3]);
            s[3][0] = fmaf(a3, bv.x, s[3][0]); s[3][1] = fmaf(a3, bv.y, s[3][1]);
            s[3][2] = fmaf(a3, bv.z, s[3][2]); s[3][3] = fmaf(a3, bv.w, s[3][3]);
        }

        #pragma unroll
        for (int i = 0; i < 4; i++) {
            int qi = q0 + ty*4 + i;
            #pragma unroll
            for (int j = 0; j < 4; j++) {
                int kj = k0 + tx*4 + j;
                int rel = kj - qi;
                rel = min(max(rel, -MAXREL), MAXREL) + MAXREL;
                float val = s[i][j]*scale + biasv[rel];
                if (!maskv[tx*4+j]) val = -10000.f;
                S[(ty*4+i)*SP + tx*4 + j] = val;
            }
        }
        __syncthreads();

        {
            int wd  = tid >> 5;
            int lane = tid & 31;
            #pragma unroll
            for (int rr = 0; rr < 8; rr++) {
                int row = wd*8 + rr;
                float v0 = S[row*SP + lane];
                float v1 = S[row*SP + lane + 32];
                float mx = fmaxf(v0, v1);
                #pragma unroll
                for (int off = 16; off > 0; off >>= 1)
                    mx = fmaxf(mx, __shfl_xor_sync(0xffffffffu, mx, off));
                float mold = m_i[row];
                float mnew = fmaxf(mold, mx);
                float p0 = __expf(v0 - mnew);
                float p1 = __expf(v1 - mnew);
                S[row*SP + lane]      = p0;
                S[row*SP + lane + 32] = p1;
                float sum = p0 + p1;
                #pragma unroll
                for (int off = 16; off > 0; off >>= 1)
                    sum += __shfl_xor_sync(0xffffffffu, sum, off);
                __syncwarp();
                if (lane == 0) {
                    float al = __expf(mold - mnew);
                    l_i[row] = l_i[row]*al + sum;
                    m_i[row] = mnew;
                    alpha_s[row] = al;
                }
                __syncwarp();
            }
        }
        __syncthreads();

        float al0 = alpha_s[ty*4+0];
        float al1 = alpha_s[ty*4+1];
        float al2 = alpha_s[ty*4+2];
        float al3 = alpha_s[ty*4+3];
        #pragma unroll
        for (int j = 0; j < 4; j++) {
            o[0][j] *= al0; o[1][j] *= al1; o[2][j] *= al2; o[3][j] *= al3;
        }
        #pragma unroll 8
        for (int k = 0; k < BK; k++) {
            float p0 = S[(ty*4+0)*SP + k];
            float p1 = S[(ty*4+1)*SP + k];
            float p2 = S[(ty*4+2)*SP + k];
            float p3 = S[(ty*4+3)*SP + k];
            float4 vv = *(const float4*)(Vs + k*SP + tx*4);
            o[0][0] = fmaf(p0, vv.x, o[0][0]); o[0][1] = fmaf(p0, vv.y, o[0][1]);
            o[0][2] = fmaf(p0, vv.z, o[0][2]); o[0][3] = fmaf(p0, vv.w, o[0][3]);
            o[1][0] = fmaf(p1, vv.x, o[1][0]); o[1][1] = fmaf(p1, vv.y, o[1][1]);
            o[1][2] = fmaf(p1, vv.z, o[1][2]); o[1][3] = fmaf(p1, vv.w, o[1][3]);
            o[2][0] = fmaf(p2, vv.x, o[2][0]); o[2][1] = fmaf(p2, vv.y, o[2][1]);
            o[2][2] = fmaf(p2, vv.z, o[2][2]); o[2][3] = fmaf(p2, vv.w, o[2][3]);
            o[3][0] = fmaf(p3, vv.x, o[3][0]); o[3][1] = fmaf(p3, vv.y, o[3][1]);
            o[3][2] = fmaf(p3, vv.z, o[3][2]); o[3][3] = fmaf(p3, vv.w, o[3][3]);
        }
    }

    #pragma unroll
    for (int i = 0; i < 4; i++) {
        int row = ty*4 + i;
        float linv = 1.f / l_i[row];
        float4 rr;
        rr.x = o[i][0]*linv; rr.y = o[i][1]*linv;
        rr.z = o[i][2]*linv; rr.w = o[i][3]*linv;
        *(float4*)&Out[(size_t)(b*TT + q0 + row)*HH + h*HD + tx*4] = rr;
    }
}

// ---------------------------------------------------------------------------
extern "C" void kernel_launch(void* const* d_in, const int* in_sizes, int n_in,
                              void* d_out, int out_size)
{
    const float* x         = (const float*)d_in[0];
    const int*   text_mask = (const int*)  d_in[1];
    const float* Wq        = (const float*)d_in[2];
    const float* bq        = (const float*)d_in[3];
    const float* Wk        = (const float*)d_in[4];
    const float* bk        = (const float*)d_in[5];
    const float* Wv        = (const float*)d_in[6];
    const float* bv        = (const float*)d_in[7];
    const float* Wo        = (const float*)d_in[8];
    const float* bo        = (const float*)d_in[9];
    const float* rel_bias  = (const float*)d_in[10];
    float* out = (float*)d_out;

    float *Qp, *Kp, *Vp, *Hp;
    cudaGetSymbolAddress((void**)&Qp, g_Q);
    cudaGetSymbolAddress((void**)&Kp, g_K);
    cudaGetSymbolAddress((void**)&Vp, g_V);
    cudaGetSymbolAddress((void**)&Hp, g_Hid);

    const int M = BB * TT;
    dim3 gdim(HH/128, M/128);

    cudaFuncSetAttribute(gemm_mma_kernel, cudaFuncAttributeMaxDynamicSharedMemorySize, GEMM_SMEM);
    cudaFuncSetAttribute(attn_kernel, cudaFuncAttributeMaxDynamicSharedMemorySize, ATTN_SMEM);

    gemm_mma_kernel<<<gdim, 256, GEMM_SMEM>>>(x, Wq, bq, Qp, nullptr, HH);
    gemm_mma_kernel<<<gdim, 256, GEMM_SMEM>>>(x, Wk, bk, Kp, nullptr, HH);
    gemm_mma_kernel<<<gdim, 256, GEMM_SMEM>>>(x, Wv, bv, Vp, nullptr, HH);

    attn_kernel<<<dim3(TT/BQ, NH, BB), 256, ATTN_SMEM>>>(Qp, Kp, Vp, text_mask, rel_bias, Hp);

    gemm_mma_kernel<<<gdim, 256, GEMM_SMEM>>>(Hp, Wo, bo, out, text_mask, HH);
}

// round 4
// speedup vs baseline: 2.4464x; 1.8504x over previous
#include <cuda_runtime.h>
#include <cuda_bf16.h>
#include <math.h>
#include <stdint.h>

#define BB 2
#define TT 2048
#define HH 1024
#define NH 16
#define HD 64
#define MAXREL 4

// Scratch (static device globals — no allocation in kernel_launch)
__device__ float g_Q[BB*TT*HH];
__device__ float g_K[BB*TT*HH];
__device__ float g_V[BB*TT*HH];
__device__ float g_Hid[BB*TT*HH];

// ===========================================================================
// Helpers (portable PTX only — nothing arch-'a'-gated)
// ===========================================================================
__device__ __forceinline__ uint32_t smem_u32(const void* p) {
    uint32_t a;
    asm("{ .reg .u64 t; cvta.to.shared.u64 t, %1; cvt.u32.u64 %0, t; }" : "=r"(a) : "l"(p));
    return a;
}
__device__ __forceinline__ void ldsm_x4(uint32_t& r0, uint32_t& r1, uint32_t& r2, uint32_t& r3,
                                        uint32_t addr) {
    asm volatile("ldmatrix.sync.aligned.m8n8.x4.shared.b16 {%0,%1,%2,%3}, [%4];"
                 : "=r"(r0), "=r"(r1), "=r"(r2), "=r"(r3) : "r"(addr));
}
__device__ __forceinline__ void mma16816(float* c, const uint32_t* a, uint32_t b0, uint32_t b1) {
    asm volatile(
        "mma.sync.aligned.m16n8k16.row.col.f32.bf16.bf16.f32 "
        "{%0,%1,%2,%3}, {%4,%5,%6,%7}, {%8,%9}, {%0,%1,%2,%3};"
        : "+f"(c[0]), "+f"(c[1]), "+f"(c[2]), "+f"(c[3])
        : "r"(a[0]), "r"(a[1]), "r"(a[2]), "r"(a[3]), "r"(b0), "r"(b1));
}
// bf16 hi/lo split pack: hi = {bf16(x) low-half, bf16(y) high-half}, lo = residuals
__device__ __forceinline__ void split2(float x, float y, uint32_t& hi, uint32_t& lo) {
    float hx = __bfloat162float(__float2bfloat16(x));
    float hy = __bfloat162float(__float2bfloat16(y));
    asm("cvt.rn.bf16x2.f32 %0, %1, %2;" : "=r"(hi) : "f"(hy), "f"(hx));
    asm("cvt.rn.bf16x2.f32 %0, %1, %2;" : "=r"(lo) : "f"(y - hy), "f"(x - hx));
}

// ===========================================================================
// mma.sync GEMM (unchanged from R3 — passed at ~105us each)
// ===========================================================================
#define GK 1024
#define KC 32
#define NCHUNK (GK / KC)
#define ROWB 80
#define TILEB (128 * ROWB)
#define BUFB (4 * TILEB)
#define GEMM_SMEM (2 * BUFB)

__global__ __launch_bounds__(256) void gemm_mma_kernel(
    const float* __restrict__ A, const float* __restrict__ W,
    const float* __restrict__ bias, float* __restrict__ C,
    const int* __restrict__ mask, int N)
{
    extern __shared__ char smemraw[];
    uint32_t* sm32 = (uint32_t*)smemraw;
    const uint32_t sbase = smem_u32(smemraw);

    const int tid  = threadIdx.x;
    const int lane = tid & 31;
    const int wid  = tid >> 5;
    const int wm   = wid & 3;
    const int wn   = wid >> 2;
    const int mbase = blockIdx.y * 128;
    const int nbase = blockIdx.x * 128;

    const int lr   = tid >> 1;
    const int half = tid & 1;
    const float* Ap = A + (size_t)(mbase + lr) * GK + half * 16;
    const float* Wp = W + (size_t)(nbase + lr) * GK + half * 16;
    const int rowoff = lr * (ROWB/4) + half * 8;

    float acc[2][8][4];
    #pragma unroll
    for (int mi = 0; mi < 2; mi++)
        #pragma unroll
        for (int j = 0; j < 8; j++)
            #pragma unroll
            for (int e = 0; e < 4; e++) acc[mi][j][e] = 0.f;

    float4 av[4], wv[4];

    const uint32_t aA = sbase + (uint32_t)(wm*32 + (lane & 15)) * ROWB + ((lane >> 4) * 16);
    const uint32_t aB = sbase + 2*TILEB
                      + (uint32_t)(wn*64 + ((lane >> 4) << 3) + (lane & 7)) * ROWB
                      + (((lane >> 3) & 1) * 16);

    #pragma unroll
    for (int i = 0; i < 4; i++) {
        av[i] = *(const float4*)(Ap + i*4);
        wv[i] = *(const float4*)(Wp + i*4);
    }
    {
        uint32_t hi[8], lo[8];
        #pragma unroll
        for (int i = 0; i < 4; i++) { split2(av[i].x, av[i].y, hi[2*i], lo[2*i]);
                                      split2(av[i].z, av[i].w, hi[2*i+1], lo[2*i+1]); }
        *(uint4*)&sm32[rowoff]                = make_uint4(hi[0],hi[1],hi[2],hi[3]);
        *(uint4*)&sm32[rowoff + 4]            = make_uint4(hi[4],hi[5],hi[6],hi[7]);
        *(uint4*)&sm32[TILEB/4 + rowoff]      = make_uint4(lo[0],lo[1],lo[2],lo[3]);
        *(uint4*)&sm32[TILEB/4 + rowoff + 4]  = make_uint4(lo[4],lo[5],lo[6],lo[7]);
        #pragma unroll
        for (int i = 0; i < 4; i++) { split2(wv[i].x, wv[i].y, hi[2*i], lo[2*i]);
                                      split2(wv[i].z, wv[i].w, hi[2*i+1], lo[2*i+1]); }
        *(uint4*)&sm32[2*TILEB/4 + rowoff]    = make_uint4(hi[0],hi[1],hi[2],hi[3]);
        *(uint4*)&sm32[2*TILEB/4 + rowoff+4]  = make_uint4(hi[4],hi[5],hi[6],hi[7]);
        *(uint4*)&sm32[3*TILEB/4 + rowoff]    = make_uint4(lo[0],lo[1],lo[2],lo[3]);
        *(uint4*)&sm32[3*TILEB/4 + rowoff+4]  = make_uint4(lo[4],lo[5],lo[6],lo[7]);
    }
    __syncthreads();

    for (int c = 0; c < NCHUNK; c++) {
        if (c + 1 < NCHUNK) {
            const float* ap = Ap + (c+1) * KC;
            const float* wp = Wp + (c+1) * KC;
            #pragma unroll
            for (int i = 0; i < 4; i++) { av[i] = *(const float4*)(ap + i*4);
                                          wv[i] = *(const float4*)(wp + i*4); }
        }

        const uint32_t boff = (uint32_t)(c & 1) * BUFB;
        #pragma unroll
        for (int ks = 0; ks < 2; ks++) {
            uint32_t Ah[2][4], Al[2][4];
            ldsm_x4(Ah[0][0],Ah[0][1],Ah[0][2],Ah[0][3], aA + boff + ks*32);
            ldsm_x4(Ah[1][0],Ah[1][1],Ah[1][2],Ah[1][3], aA + boff + 16*ROWB + ks*32);
            ldsm_x4(Al[0][0],Al[0][1],Al[0][2],Al[0][3], aA + boff + TILEB + ks*32);
            ldsm_x4(Al[1][0],Al[1][1],Al[1][2],Al[1][3], aA + boff + TILEB + 16*ROWB + ks*32);
            #pragma unroll
            for (int jp = 0; jp < 4; jp++) {
                uint32_t Bh[4], Bl[4];
                ldsm_x4(Bh[0],Bh[1],Bh[2],Bh[3], aB + boff + jp*16*ROWB + ks*32);
                ldsm_x4(Bl[0],Bl[1],Bl[2],Bl[3], aB + boff + TILEB + jp*16*ROWB + ks*32);
                #pragma unroll
                for (int mi = 0; mi < 2; mi++) {
                    mma16816(acc[mi][2*jp],   Ah[mi], Bh[0], Bh[1]);
                    mma16816(acc[mi][2*jp],   Ah[mi], Bl[0], Bl[1]);
                    mma16816(acc[mi][2*jp],   Al[mi], Bh[0], Bh[1]);
                    mma16816(acc[mi][2*jp+1], Ah[mi], Bh[2], Bh[3]);
                    mma16816(acc[mi][2*jp+1], Ah[mi], Bl[2], Bl[3]);
                    mma16816(acc[mi][2*jp+1], Al[mi], Bh[2], Bh[3]);
                }
            }
        }

        if (c + 1 < NCHUNK) {
            const uint32_t sb = (uint32_t)((c+1) & 1) * (BUFB/4);
            uint32_t hi[8], lo[8];
            #pragma unroll
            for (int i = 0; i < 4; i++) { split2(av[i].x, av[i].y, hi[2*i], lo[2*i]);
                                          split2(av[i].z, av[i].w, hi[2*i+1], lo[2*i+1]); }
            *(uint4*)&sm32[sb + rowoff]               = make_uint4(hi[0],hi[1],hi[2],hi[3]);
            *(uint4*)&sm32[sb + rowoff + 4]           = make_uint4(hi[4],hi[5],hi[6],hi[7]);
            *(uint4*)&sm32[sb + TILEB/4 + rowoff]     = make_uint4(lo[0],lo[1],lo[2],lo[3]);
            *(uint4*)&sm32[sb + TILEB/4 + rowoff + 4] = make_uint4(lo[4],lo[5],lo[6],lo[7]);
            #pragma unroll
            for (int i = 0; i < 4; i++) { split2(wv[i].x, wv[i].y, hi[2*i], lo[2*i]);
                                          split2(wv[i].z, wv[i].w, hi[2*i+1], lo[2*i+1]); }
            *(uint4*)&sm32[sb + 2*TILEB/4 + rowoff]   = make_uint4(hi[0],hi[1],hi[2],hi[3]);
            *(uint4*)&sm32[sb + 2*TILEB/4 + rowoff+4] = make_uint4(hi[4],hi[5],hi[6],hi[7]);
            *(uint4*)&sm32[sb + 3*TILEB/4 + rowoff]   = make_uint4(lo[0],lo[1],lo[2],lo[3]);
            *(uint4*)&sm32[sb + 3*TILEB/4 + rowoff+4] = make_uint4(lo[4],lo[5],lo[6],lo[7]);
        }
        __syncthreads();
    }

    #pragma unroll
    for (int mi = 0; mi < 2; mi++) {
        const int r0 = mbase + wm*32 + mi*16 + (lane >> 2);
        const float mv0 = mask ? (float)mask[r0]     : 1.f;
        const float mv1 = mask ? (float)mask[r0 + 8] : 1.f;
        #pragma unroll
        for (int j = 0; j < 8; j++) {
            const int col = nbase + wn*64 + j*8 + (lane & 3)*2;
            const float b0 = bias[col], b1 = bias[col+1];
            float2 o0 = make_float2((acc[mi][j][0] + b0) * mv0, (acc[mi][j][1] + b1) * mv0);
            float2 o1 = make_float2((acc[mi][j][2] + b0) * mv1, (acc[mi][j][3] + b1) * mv1);
            *(float2*)&C[(size_t)r0 * N + col]       = o0;
            *(float2*)&C[(size_t)(r0+8) * N + col]   = o1;
        }
    }
}

// ===========================================================================
// Tensor-core flash attention. CTA = (b, h, 128 q-rows), 8 warps x m16.
// S and O register-resident; Q/K/V bf16 hi/lo in SMEM (144B stride).
// ===========================================================================
#define BQ2 128
#define BK2 64
#define STRD 144
#define O_QHI 0
#define O_QLO (O_QHI + BQ2*STRD)
#define O_KHI (O_QLO + BQ2*STRD)
#define O_KLO (O_KHI + BK2*STRD)
#define O_VHI (O_KLO + BK2*STRD)
#define O_VLO (O_VHI + BK2*STRD)
#define O_KADD (O_VLO + BK2*STRD)
#define ATT_SMEM (O_KADD + BK2*4)

__global__ __launch_bounds__(256) void attn_mma_kernel(
    const float* __restrict__ Q, const float* __restrict__ Kg,
    const float* __restrict__ V, const int* __restrict__ mask,
    const float* __restrict__ rel_bias, float* __restrict__ Out)
{
    extern __shared__ char sm[];
    const uint32_t sb = smem_u32(sm);
    float* kaddp = (float*)(sm + O_KADD);
    __shared__ float sbias[9];

    const int tid  = threadIdx.x;
    const int lane = tid & 31;
    const int wid  = tid >> 5;
    const int b    = blockIdx.z;
    const int h    = blockIdx.y;
    const int q0   = blockIdx.x * BQ2;
    const float scale = 0.125f;

    if (tid < 9) sbias[tid] = rel_bias[tid*NH + h];

    // ---- load Q tile (128x64 fp32) -> bf16 hi/lo SMEM
    {
        const int r = tid >> 1, half = tid & 1;
        const float* src = Q + (size_t)(b*TT + q0 + r)*HH + h*HD + half*32;
        uint32_t hi[16], lo[16];
        #pragma unroll
        for (int i = 0; i < 8; i++) {
            float4 v = *(const float4*)(src + i*4);
            split2(v.x, v.y, hi[2*i], lo[2*i]);
            split2(v.z, v.w, hi[2*i+1], lo[2*i+1]);
        }
        char* dq = sm + (size_t)r*STRD + half*64;
        #pragma unroll
        for (int i = 0; i < 4; i++) {
            *(uint4*)(dq + O_QHI + i*16) = *(uint4*)&hi[4*i];
            *(uint4*)(dq + O_QLO + i*16) = *(uint4*)&lo[4*i];
        }
    }
    __syncthreads();

    // ---- Q A-fragments resident in registers (invariant over k-loop)
    uint32_t qh[4][4], ql[4][4];
    {
        const uint32_t aQ = sb + (uint32_t)(wid*16 + (lane & 15))*STRD + (lane >> 4)*16;
        #pragma unroll
        for (int ks = 0; ks < 4; ks++) {
            ldsm_x4(qh[ks][0], qh[ks][1], qh[ks][2], qh[ks][3], aQ + O_QHI + ks*32);
            ldsm_x4(ql[ks][0], ql[ks][1], ql[ks][2], ql[ks][3], aQ + O_QLO + ks*32);
        }
    }
    const float bias0 = sbias[0], bias8 = sbias[8];

    // B-fragment base addresses (row term shared by K and Vt tiles)
    const uint32_t bRow = (uint32_t)(((lane >> 4) << 3) + (lane & 7))*STRD
                        + ((lane >> 3) & 1)*16;

    const int cb = (lane & 3) * 2;          // col pair base within n8
    const int r1 = lane >> 2;               // row within m16 (and r1+8)
    const int qi1 = q0 + wid*16 + r1;

    float o[8][4];
    #pragma unroll
    for (int j = 0; j < 8; j++)
        #pragma unroll
        for (int e = 0; e < 4; e++) o[j][e] = 0.f;
    float m1 = -INFINITY, m2 = -INFINITY, l1 = 0.f, l2 = 0.f;

    for (int kt = 0; kt < TT/BK2; kt++) {
        const int k0 = kt * BK2;
        __syncthreads();   // prior iteration's ldsm reads complete

        // ---- K tile (64x64) -> hi/lo SMEM, natural layout
        {
            const int r = tid >> 2, q4 = tid & 3;
            const float* src = Kg + (size_t)(b*TT + k0 + r)*HH + h*HD + q4*16;
            uint32_t hi[8], lo[8];
            #pragma unroll
            for (int i = 0; i < 4; i++) {
                float4 v = *(const float4*)(src + i*4);
                split2(v.x, v.y, hi[2*i], lo[2*i]);
                split2(v.z, v.w, hi[2*i+1], lo[2*i+1]);
            }
            char* dk = sm + (size_t)r*STRD + q4*32;
            *(uint4*)(dk + O_KHI)      = *(uint4*)&hi[0];
            *(uint4*)(dk + O_KHI + 16) = *(uint4*)&hi[4];
            *(uint4*)(dk + O_KLO)      = *(uint4*)&lo[0];
            *(uint4*)(dk + O_KLO + 16) = *(uint4*)&lo[4];
        }
        // ---- V tile transposed: Vt[dim][key], key-pairs packed in bf16x2
        {
            const int a  = tid & 31;           // key pair (2a, 2a+1)
            const int d0 = (tid >> 5) * 8;     // 8 dims per thread
            const float* va = V + (size_t)(b*TT + k0 + 2*a)*HH + h*HD + d0;
            float4 va0 = *(const float4*)(va);
            float4 va1 = *(const float4*)(va + 4);
            float4 vb0 = *(const float4*)(va + HH);
            float4 vb1 = *(const float4*)(va + HH + 4);
            const float* fa0 = (const float*)&va0;
            const float* fa1 = (const float*)&va1;
            const float* fb0 = (const float*)&vb0;
            const float* fb1 = (const float*)&vb1;
            #pragma unroll
            for (int i = 0; i < 4; i++) {
                uint32_t hi, lo;
                split2(fa0[i], fb0[i], hi, lo);
                *(uint32_t*)(sm + O_VHI + (size_t)(d0+i)*STRD + a*4) = hi;
                *(uint32_t*)(sm + O_VLO + (size_t)(d0+i)*STRD + a*4) = lo;
                split2(fa1[i], fb1[i], hi, lo);
                *(uint32_t*)(sm + O_VHI + (size_t)(d0+4+i)*STRD + a*4) = hi;
                *(uint32_t*)(sm + O_VLO + (size_t)(d0+4+i)*STRD + a*4) = lo;
            }
        }
        if (tid < BK2) kaddp[tid] = mask[b*TT + k0 + tid] ? 0.f : -30000.f;
        __syncthreads();

        // ---- S = Q K^T (3-MMA hi/lo)
        float s[8][4];
        #pragma unroll
        for (int j = 0; j < 8; j++)
            #pragma unroll
            for (int e = 0; e < 4; e++) s[j][e] = 0.f;

        #pragma unroll
        for (int ks = 0; ks < 4; ks++) {
            #pragma unroll
            for (int jp = 0; jp < 4; jp++) {
                uint32_t Bh[4], Bl[4];
                const uint32_t ab = sb + (uint32_t)(jp*16)*STRD + bRow + ks*32;
                ldsm_x4(Bh[0],Bh[1],Bh[2],Bh[3], ab + O_KHI);
                ldsm_x4(Bl[0],Bl[1],Bl[2],Bl[3], ab + O_KLO);
                mma16816(s[2*jp],   qh[ks], Bh[0], Bh[1]);
                mma16816(s[2*jp],   qh[ks], Bl[0], Bl[1]);
                mma16816(s[2*jp],   ql[ks], Bh[0], Bh[1]);
                mma16816(s[2*jp+1], qh[ks], Bh[2], Bh[3]);
                mma16816(s[2*jp+1], qh[ks], Bl[2], Bl[3]);
                mma16816(s[2*jp+1], ql[ks], Bh[2], Bh[3]);
            }
        }

        // ---- scale + rel-bias + key-mask
        float bconst = 0.f;
        bool midband = false;
        if (k0 + BK2 - 1 <= q0 - 4)       bconst = bias0;
        else if (k0 >= q0 + BQ2 - 1 + 4)  bconst = bias8;
        else                               midband = true;

        float vmax1 = -INFINITY, vmax2 = -INFINITY;
        #pragma unroll
        for (int j = 0; j < 8; j++) {
            const float a0 = kaddp[8*j + cb], a1 = kaddp[8*j + cb + 1];
            float b00, b01, b10, b11;
            if (!midband) { b00 = b01 = b10 = b11 = bconst; }
            else {
                int d = k0 + 8*j + cb - qi1 + 4;
                b00 = sbias[min(max(d,   0), 8)];
                b01 = sbias[min(max(d+1, 0), 8)];
                b10 = sbias[min(max(d-8, 0), 8)];
                b11 = sbias[min(max(d-7, 0), 8)];
            }
            s[j][0] = fmaf(s[j][0], scale, a0 + b00);
            s[j][1] = fmaf(s[j][1], scale, a1 + b01);
            s[j][2] = fmaf(s[j][2], scale, a0 + b10);
            s[j][3] = fmaf(s[j][3], scale, a1 + b11);
            vmax1 = fmaxf(vmax1, fmaxf(s[j][0], s[j][1]));
            vmax2 = fmaxf(vmax2, fmaxf(s[j][2], s[j][3]));
        }
        vmax1 = fmaxf(vmax1, __shfl_xor_sync(0xffffffffu, vmax1, 1));
        vmax1 = fmaxf(vmax1, __shfl_xor_sync(0xffffffffu, vmax1, 2));
        vmax2 = fmaxf(vmax2, __shfl_xor_sync(0xffffffffu, vmax2, 1));
        vmax2 = fmaxf(vmax2, __shfl_xor_sync(0xffffffffu, vmax2, 2));

        const float mn1 = fmaxf(m1, vmax1);
        const float mn2 = fmaxf(m2, vmax2);
        const float al1 = __expf(m1 - mn1);
        const float al2 = __expf(m2 - mn2);
        float sum1 = 0.f, sum2 = 0.f;
        #pragma unroll
        for (int j = 0; j < 8; j++) {
            s[j][0] = __expf(s[j][0] - mn1);
            s[j][1] = __expf(s[j][1] - mn1);
            s[j][2] = __expf(s[j][2] - mn2);
            s[j][3] = __expf(s[j][3] - mn2);
            sum1 += s[j][0] + s[j][1];
            sum2 += s[j][2] + s[j][3];
        }
        sum1 += __shfl_xor_sync(0xffffffffu, sum1, 1);
        sum1 += __shfl_xor_sync(0xffffffffu, sum1, 2);
        sum2 += __shfl_xor_sync(0xffffffffu, sum2, 1);
        sum2 += __shfl_xor_sync(0xffffffffu, sum2, 2);
        l1 = l1*al1 + sum1;  m1 = mn1;
        l2 = l2*al2 + sum2;  m2 = mn2;

        #pragma unroll
        for (int j = 0; j < 8; j++) {
            o[j][0] *= al1; o[j][1] *= al1;
            o[j][2] *= al2; o[j][3] *= al2;
        }

        // ---- O += P V (3-MMA hi/lo); P packed from s-regs (FA2 layout match)
        #pragma unroll
        for (int kc = 0; kc < 4; kc++) {
            uint32_t Ph[4], Pl[4];
            split2(s[2*kc][0],   s[2*kc][1],   Ph[0], Pl[0]);
            split2(s[2*kc][2],   s[2*kc][3],   Ph[1], Pl[1]);
            split2(s[2*kc+1][0], s[2*kc+1][1], Ph[2], Pl[2]);
            split2(s[2*kc+1][2], s[2*kc+1][3], Ph[3], Pl[3]);
            #pragma unroll
            for (int jp = 0; jp < 4; jp++) {
                uint32_t Bh[4], Bl[4];
                const uint32_t ab = sb + (uint32_t)(jp*16)*STRD + bRow + kc*32;
                ldsm_x4(Bh[0],Bh[1],Bh[2],Bh[3], ab + O_VHI);
                ldsm_x4(Bl[0],Bl[1],Bl[2],Bl[3], ab + O_VLO);
                mma16816(o[2*jp],   Ph, Bh[0], Bh[1]);
                mma16816(o[2*jp],   Ph, Bl[0], Bl[1]);
                mma16816(o[2*jp],   Pl, Bh[0], Bh[1]);
                mma16816(o[2*jp+1], Ph, Bh[2], Bh[3]);
                mma16816(o[2*jp+1], Ph, Bl[2], Bl[3]);
                mma16816(o[2*jp+1], Pl, Bh[2], Bh[3]);
            }
        }
    }

    // ---- epilogue: divide by l, write fp32 hidden
    const float inv1 = 1.f / l1, inv2 = 1.f / l2;
    float* out1 = Out + (size_t)(b*TT + qi1)*HH + h*HD + cb;
    float* out2 = out1 + (size_t)8*HH;
    #pragma unroll
    for (int j = 0; j < 8; j++) {
        *(float2*)(out1 + 8*j) = make_float2(o[j][0]*inv1, o[j][1]*inv1);
        *(float2*)(out2 + 8*j) = make_float2(o[j][2]*inv2, o[j][3]*inv2);
    }
}

// ---------------------------------------------------------------------------
extern "C" void kernel_launch(void* const* d_in, const int* in_sizes, int n_in,
                              void* d_out, int out_size)
{
    const float* x         = (const float*)d_in[0];
    const int*   text_mask = (const int*)  d_in[1];
    const float* Wq        = (const float*)d_in[2];
    const float* bq        = (const float*)d_in[3];
    const float* Wk        = (const float*)d_in[4];
    const float* bk        = (const float*)d_in[5];
    const float* Wv        = (const float*)d_in[6];
    const float* bv        = (const float*)d_in[7];
    const float* Wo        = (const float*)d_in[8];
    const float* bo        = (const float*)d_in[9];
    const float* rel_bias  = (const float*)d_in[10];
    float* out = (float*)d_out;

    float *Qp, *Kp, *Vp, *Hp;
    cudaGetSymbolAddress((void**)&Qp, g_Q);
    cudaGetSymbolAddress((void**)&Kp, g_K);
    cudaGetSymbolAddress((void**)&Vp, g_V);
    cudaGetSymbolAddress((void**)&Hp, g_Hid);

    const int M = BB * TT;
    dim3 gdim(HH/128, M/128);

    cudaFuncSetAttribute(gemm_mma_kernel, cudaFuncAttributeMaxDynamicSharedMemorySize, GEMM_SMEM);
    cudaFuncSetAttribute(attn_mma_kernel, cudaFuncAttributeMaxDynamicSharedMemorySize, ATT_SMEM);

    gemm_mma_kernel<<<gdim, 256, GEMM_SMEM>>>(x, Wq, bq, Qp, nullptr, HH);
    gemm_mma_kernel<<<gdim, 256, GEMM_SMEM>>>(x, Wk, bk, Kp, nullptr, HH);
    gemm_mma_kernel<<<gdim, 256, GEMM_SMEM>>>(x, Wv, bv, Vp, nullptr, HH);

    attn_mma_kernel<<<dim3(TT/BQ2, NH, BB), 256, ATT_SMEM>>>(Qp, Kp, Vp, text_mask, rel_bias, Hp);

    gemm_mma_kernel<<<gdim, 256, GEMM_SMEM>>>(Hp, Wo, bo, out, text_mask, HH);
}

// round 5
// speedup vs baseline: 2.9038x; 1.1869x over previous
#include <cuda_runtime.h>
#include <cuda_bf16.h>
#include <math.h>
#include <stdint.h>

#define BB 2
#define TT 2048
#define HH 1024
#define NH 16
#define HD 64
#define MAXREL 4

// ---- bf16 hi/lo scratch (uint32 = bf16x2), static device globals ----
#define NTOK (BB*TT)
__device__ uint32_t g_xhi[NTOK*HH/2],  g_xlo[NTOK*HH/2];
__device__ uint32_t g_Qhi[NTOK*HH/2],  g_Qlo[NTOK*HH/2];
__device__ uint32_t g_Khi[NTOK*HH/2],  g_Klo[NTOK*HH/2];
__device__ uint32_t g_Vhi[NTOK*HH/2],  g_Vlo[NTOK*HH/2];
__device__ uint32_t g_Hhi[NTOK*HH/2],  g_Hlo[NTOK*HH/2];
__device__ uint32_t g_Wqhi[HH*HH/2], g_Wqlo[HH*HH/2];
__device__ uint32_t g_Wkhi[HH*HH/2], g_Wklo[HH*HH/2];
__device__ uint32_t g_Wvhi[HH*HH/2], g_Wvlo[HH*HH/2];
__device__ uint32_t g_Wohi[HH*HH/2], g_Wolo[HH*HH/2];

// ===========================================================================
// Helpers (portable PTX only)
// ===========================================================================
__device__ __forceinline__ uint32_t smem_u32(const void* p) {
    uint32_t a;
    asm("{ .reg .u64 t; cvta.to.shared.u64 t, %1; cvt.u32.u64 %0, t; }" : "=r"(a) : "l"(p));
    return a;
}
__device__ __forceinline__ void ldsm_x4(uint32_t& r0, uint32_t& r1, uint32_t& r2, uint32_t& r3,
                                        uint32_t addr) {
    asm volatile("ldmatrix.sync.aligned.m8n8.x4.shared.b16 {%0,%1,%2,%3}, [%4];"
                 : "=r"(r0), "=r"(r1), "=r"(r2), "=r"(r3) : "r"(addr));
}
__device__ __forceinline__ void ldsm_x4_t(uint32_t& r0, uint32_t& r1, uint32_t& r2, uint32_t& r3,
                                          uint32_t addr) {
    asm volatile("ldmatrix.sync.aligned.m8n8.x4.trans.shared.b16 {%0,%1,%2,%3}, [%4];"
                 : "=r"(r0), "=r"(r1), "=r"(r2), "=r"(r3) : "r"(addr));
}
__device__ __forceinline__ void mma16816(float* c, const uint32_t* a, uint32_t b0, uint32_t b1) {
    asm volatile(
        "mma.sync.aligned.m16n8k16.row.col.f32.bf16.bf16.f32 "
        "{%0,%1,%2,%3}, {%4,%5,%6,%7}, {%8,%9}, {%0,%1,%2,%3};"
        : "+f"(c[0]), "+f"(c[1]), "+f"(c[2]), "+f"(c[3])
        : "r"(a[0]), "r"(a[1]), "r"(a[2]), "r"(a[3]), "r"(b0), "r"(b1));
}
__device__ __forceinline__ void split2(float x, float y, uint32_t& hi, uint32_t& lo) {
    float hx = __bfloat162float(__float2bfloat16(x));
    float hy = __bfloat162float(__float2bfloat16(y));
    asm("cvt.rn.bf16x2.f32 %0, %1, %2;" : "=r"(hi) : "f"(hy), "f"(hx));
    asm("cvt.rn.bf16x2.f32 %0, %1, %2;" : "=r"(lo) : "f"(y - hy), "f"(x - hx));
}
__device__ __forceinline__ void cp_async16(uint32_t d, const void* g) {
    asm volatile("cp.async.cg.shared.global [%0], [%1], 16;" :: "r"(d), "l"(g));
}
__device__ __forceinline__ void cp_commit() {
    asm volatile("cp.async.commit_group;" ::: "memory");
}
template<int W> __device__ __forceinline__ void cp_wait() {
    asm volatile("cp.async.wait_group %0;" :: "n"(W) : "memory");
}

// ===========================================================================
// fp32 -> bf16 hi/lo split (pre-pass)
// ===========================================================================
__global__ void split_kernel(const float* __restrict__ src,
                             uint32_t* __restrict__ hi, uint32_t* __restrict__ lo, int n2)
{
    int i = blockIdx.x * blockDim.x + threadIdx.x;
    if (i < n2) {
        float2 v = ((const float2*)src)[i];
        uint32_t h, l;
        split2(v.x, v.y, h, l);
        hi[i] = h; lo[i] = l;
    }
}

// ===========================================================================
// bf16 hi/lo GEMM: C[M,N] = (A)(W)^T + bias. A,W pre-split bf16x2 arrays.
// CTA 128x128, K-chunk 32, cp.async double buffer, 3-MMA hi/lo.
// Output either fp32 (masked) or bf16 hi/lo.
// ===========================================================================
#define GK 1024
#define KC 32
#define NCHUNK (GK / KC)
#define GROWB 80                 // smem row stride bytes (64B data + 16 pad)
#define GTILE (128 * GROWB)      // 10240
#define GBUF  (4 * GTILE)        // Ahi|Alo|Whi|Wlo = 40960
#define GEMM_SMEM (2 * GBUF)     // 81920

__global__ __launch_bounds__(256, 2) void gemm_bf16_kernel(
    const uint32_t* __restrict__ Ahi, const uint32_t* __restrict__ Alo,
    const uint32_t* __restrict__ Whi, const uint32_t* __restrict__ Wlo,
    const float* __restrict__ bias,
    float* __restrict__ Cf, uint32_t* __restrict__ Chi, uint32_t* __restrict__ Clo,
    const int* __restrict__ mask, int N)
{
    extern __shared__ char smemraw[];
    const uint32_t sbase = smem_u32(smemraw);

    const int tid  = threadIdx.x;
    const int lane = tid & 31;
    const int wid  = tid >> 5;
    const int wm   = wid & 3;
    const int wn   = wid >> 2;
    const int mbase = blockIdx.y * 128;
    const int nbase = blockIdx.x * 128;

    // cp.async mapping: row = tid>>1, half-row (32B) = tid&1
    const int lr = tid >> 1, half = tid & 1;
    const uint32_t* gAh = Ahi + ((size_t)(mbase + lr) << 9) + half * 8;
    const uint32_t* gAl = Alo + ((size_t)(mbase + lr) << 9) + half * 8;
    const uint32_t* gWh = Whi + ((size_t)(nbase + lr) << 9) + half * 8;
    const uint32_t* gWl = Wlo + ((size_t)(nbase + lr) << 9) + half * 8;
    const uint32_t sdst = sbase + lr * GROWB + half * 32;

    float acc[2][8][4];
    #pragma unroll
    for (int mi = 0; mi < 2; mi++)
        #pragma unroll
        for (int j = 0; j < 8; j++)
            #pragma unroll
            for (int e = 0; e < 4; e++) acc[mi][j][e] = 0.f;

    const uint32_t aA = sbase + (uint32_t)(wm*32 + (lane & 15)) * GROWB + ((lane >> 4) * 16);
    const uint32_t aB = sbase + 2*GTILE
                      + (uint32_t)(wn*64 + ((lane >> 4) << 3) + (lane & 7)) * GROWB
                      + (((lane >> 3) & 1) * 16);

    // prologue: issue chunk 0 into buf 0
    {
        const int off = 0;
        cp_async16(sdst,               gAh + off); cp_async16(sdst + 16,           gAh + off + 4);
        cp_async16(sdst + GTILE,       gAl + off); cp_async16(sdst + GTILE + 16,   gAl + off + 4);
        cp_async16(sdst + 2*GTILE,     gWh + off); cp_async16(sdst + 2*GTILE + 16, gWh + off + 4);
        cp_async16(sdst + 3*GTILE,     gWl + off); cp_async16(sdst + 3*GTILE + 16, gWl + off + 4);
        cp_commit();
    }

    for (int c = 0; c < NCHUNK; c++) {
        if (c + 1 < NCHUNK) {
            const uint32_t d = sdst + (uint32_t)((c + 1) & 1) * GBUF;
            const int off = (c + 1) * 16;
            cp_async16(d,               gAh + off); cp_async16(d + 16,           gAh + off + 4);
            cp_async16(d + GTILE,       gAl + off); cp_async16(d + GTILE + 16,   gAl + off + 4);
            cp_async16(d + 2*GTILE,     gWh + off); cp_async16(d + 2*GTILE + 16, gWh + off + 4);
            cp_async16(d + 3*GTILE,     gWl + off); cp_async16(d + 3*GTILE + 16, gWl + off + 4);
            cp_commit();
            cp_wait<1>();
        } else {
            cp_wait<0>();
        }
        __syncthreads();

        const uint32_t boff = (uint32_t)(c & 1) * GBUF;
        #pragma unroll
        for (int ks = 0; ks < 2; ks++) {
            uint32_t Ah[2][4], Al[2][4];
            ldsm_x4(Ah[0][0],Ah[0][1],Ah[0][2],Ah[0][3], aA + boff + ks*32);
            ldsm_x4(Ah[1][0],Ah[1][1],Ah[1][2],Ah[1][3], aA + boff + 16*GROWB + ks*32);
            ldsm_x4(Al[0][0],Al[0][1],Al[0][2],Al[0][3], aA + boff + GTILE + ks*32);
            ldsm_x4(Al[1][0],Al[1][1],Al[1][2],Al[1][3], aA + boff + GTILE + 16*GROWB + ks*32);
            #pragma unroll
            for (int jp = 0; jp < 4; jp++) {
                uint32_t Bh[4], Bl[4];
                ldsm_x4(Bh[0],Bh[1],Bh[2],Bh[3], aB + boff + jp*16*GROWB + ks*32);
                ldsm_x4(Bl[0],Bl[1],Bl[2],Bl[3], aB + boff + GTILE + jp*16*GROWB + ks*32);
                #pragma unroll
                for (int mi = 0; mi < 2; mi++) {
                    mma16816(acc[mi][2*jp],   Ah[mi], Bh[0], Bh[1]);
                    mma16816(acc[mi][2*jp],   Ah[mi], Bl[0], Bl[1]);
                    mma16816(acc[mi][2*jp],   Al[mi], Bh[0], Bh[1]);
                    mma16816(acc[mi][2*jp+1], Ah[mi], Bh[2], Bh[3]);
                    mma16816(acc[mi][2*jp+1], Ah[mi], Bl[2], Bl[3]);
                    mma16816(acc[mi][2*jp+1], Al[mi], Bh[2], Bh[3]);
                }
            }
        }
        __syncthreads();
    }

    // epilogue
    #pragma unroll
    for (int mi = 0; mi < 2; mi++) {
        const int r0 = mbase + wm*32 + mi*16 + (lane >> 2);
        #pragma unroll
        for (int j = 0; j < 8; j++) {
            const int col = nbase + wn*64 + j*8 + (lane & 3)*2;
            const float b0 = bias[col], b1 = bias[col+1];
            float c0 = acc[mi][j][0] + b0, c1 = acc[mi][j][1] + b1;
            float c2 = acc[mi][j][2] + b0, c3 = acc[mi][j][3] + b1;
            if (Cf) {
                const float mv0 = (float)mask[r0];
                const float mv1 = (float)mask[r0 + 8];
                *(float2*)&Cf[(size_t)r0 * N + col]     = make_float2(c0*mv0, c1*mv0);
                *(float2*)&Cf[(size_t)(r0+8) * N + col] = make_float2(c2*mv1, c3*mv1);
            } else {
                uint32_t h, l;
                split2(c0, c1, h, l);
                Chi[((size_t)r0 * N + col) >> 1] = h;
                Clo[((size_t)r0 * N + col) >> 1] = l;
                split2(c2, c3, h, l);
                Chi[((size_t)(r0+8) * N + col) >> 1] = h;
                Clo[((size_t)(r0+8) * N + col) >> 1] = l;
            }
        }
    }
}

// ===========================================================================
// bf16 flash attention: CTA = (b,h,128 q), 8 warps x m16, cp.async K/V
// double-buffer, V via trans-ldmatrix, mask as bitset, 2 CTAs/SM.
// ===========================================================================
#define BQ2 128
#define BK2 64
#define NT  (TT / BK2)
#define STRD 144
#define A_QHI 0
#define A_QLO 18432
#define A_KV  36864            // + buf*36864 ; K hi | K lo(+9216) | V hi(+18432) | V lo(+27648)
#define A_MB  110592           // 64 uint32 mask bits
#define ATT_SMEM (A_MB + 256)

__global__ __launch_bounds__(256, 2) void attn_bf16_kernel(
    const uint32_t* __restrict__ Qhi, const uint32_t* __restrict__ Qlo,
    const uint32_t* __restrict__ Khi, const uint32_t* __restrict__ Klo,
    const uint32_t* __restrict__ Vhi, const uint32_t* __restrict__ Vlo,
    const int* __restrict__ mask, const float* __restrict__ rel_bias,
    uint32_t* __restrict__ Hhi, uint32_t* __restrict__ Hlo)
{
    extern __shared__ char sm[];
    const uint32_t sb = smem_u32(sm);
    uint32_t* mbits = (uint32_t*)(sm + A_MB);
    __shared__ float sbias[9];

    const int tid  = threadIdx.x;
    const int lane = tid & 31;
    const int wid  = tid >> 5;
    const int b    = blockIdx.z;
    const int h    = blockIdx.y;
    const int q0   = blockIdx.x * BQ2;
    const float scale = 0.125f;

    if (tid < 9) sbias[tid] = rel_bias[tid*NH + h];

    // mask bitset: 2048 bits = 64 words
    #pragma unroll
    for (int i = 0; i < 8; i++) {
        int v = mask[b*TT + i*256 + tid];
        uint32_t bal = __ballot_sync(0xffffffffu, v != 0);
        if (lane == 0) mbits[i*8 + wid] = bal;
    }

    // Q tile -> SMEM (group 0)
    {
        const int r = tid >> 1, hf = tid & 1;
        const size_t g = ((size_t)(b*TT + q0 + r) * HH + h*HD) >> 1;
        const uint32_t d = sb + r*STRD + hf*64;
        const uint32_t* s0 = Qhi + g + hf*16;
        const uint32_t* s1 = Qlo + g + hf*16;
        cp_async16(d,      s0);     cp_async16(d+16, s0+4);
        cp_async16(d+32,   s0+8);   cp_async16(d+48, s0+12);
        cp_async16(d+A_QLO,    s1);    cp_async16(d+A_QLO+16, s1+4);
        cp_async16(d+A_QLO+32, s1+8);  cp_async16(d+A_QLO+48, s1+12);
        cp_commit();
    }

    // K/V tile issue helper values
    const int kvr = tid >> 2, kvq = tid & 3;
    const size_t kvg0 = ((size_t)(b*TT + kvr) * HH + h*HD) >> 1;   // + kt*64*HH/2
    const uint32_t kvd0 = sb + A_KV + kvr*STRD + kvq*32;

    #define ISSUE_KV(KT, BUF) do {                                                  \
        const size_t g_ = kvg0 + (size_t)(KT) * (64*HH/2) + kvq*8;                  \
        const uint32_t d_ = kvd0 + (uint32_t)(BUF) * 36864;                         \
        cp_async16(d_,          Khi + g_); cp_async16(d_+16,       Khi + g_ + 4);   \
        cp_async16(d_+9216,     Klo + g_); cp_async16(d_+9216+16,  Klo + g_ + 4);   \
        cp_async16(d_+18432,    Vhi + g_); cp_async16(d_+18432+16, Vhi + g_ + 4);   \
        cp_async16(d_+27648,    Vlo + g_); cp_async16(d_+27648+16, Vlo + g_ + 4);   \
        cp_commit();                                                                \
    } while (0)

    ISSUE_KV(0, 0);
    ISSUE_KV(1, 1);
    cp_wait<2>();        // Q ready
    __syncthreads();

    const uint32_t aQ   = sb + (uint32_t)(wid*16 + (lane & 15))*STRD + (lane >> 4)*16;
    const uint32_t bRow = (uint32_t)(((lane >> 4) << 3) + (lane & 7))*STRD
                        + ((lane >> 3) & 1)*16;                       // K non-trans
    const uint32_t vRow = (uint32_t)((((lane >> 3) & 1) << 3) + (lane & 7))*STRD
                        + (lane >> 4)*16;                             // V trans

    const int cb = (lane & 3) * 2;
    const int r1 = lane >> 2;
    const int qi1 = q0 + wid*16 + r1;
    const float bias0 = sbias[0], bias8 = sbias[8];

    float o[8][4];
    #pragma unroll
    for (int j = 0; j < 8; j++)
        #pragma unroll
        for (int e = 0; e < 4; e++) o[j][e] = 0.f;
    float m1 = -INFINITY, m2 = -INFINITY, l1 = 0.f, l2 = 0.f;

    for (int kt = 0; kt < NT; kt++) {
        const int k0 = kt * BK2;
        const uint32_t kb = A_KV + (uint32_t)(kt & 1) * 36864;

        if (kt + 1 < NT) cp_wait<1>(); else cp_wait<0>();
        __syncthreads();

        // ---- S = Q K^T
        float s[8][4];
        #pragma unroll
        for (int j = 0; j < 8; j++)
            #pragma unroll
            for (int e = 0; e < 4; e++) s[j][e] = 0.f;

        #pragma unroll
        for (int ks = 0; ks < 4; ks++) {
            uint32_t qh[4], ql[4];
            ldsm_x4(qh[0], qh[1], qh[2], qh[3], aQ + ks*32);
            ldsm_x4(ql[0], ql[1], ql[2], ql[3], aQ + A_QLO + ks*32);
            #pragma unroll
            for (int jp = 0; jp < 4; jp++) {
                uint32_t Bh[4], Bl[4];
                const uint32_t ab = sb + kb + (uint32_t)(jp*16)*STRD + bRow + ks*32;
                ldsm_x4(Bh[0],Bh[1],Bh[2],Bh[3], ab);
                ldsm_x4(Bl[0],Bl[1],Bl[2],Bl[3], ab + 9216);
                mma16816(s[2*jp],   qh, Bh[0], Bh[1]);
                mma16816(s[2*jp],   qh, Bl[0], Bl[1]);
                mma16816(s[2*jp],   ql, Bh[0], Bh[1]);
                mma16816(s[2*jp+1], qh, Bh[2], Bh[3]);
                mma16816(s[2*jp+1], qh, Bl[2], Bl[3]);
                mma16816(s[2*jp+1], ql, Bh[2], Bh[3]);
            }
        }

        // ---- scale + rel-bias + mask
        float bconst = 0.f;
        bool midband = false;
        if (k0 + BK2 - 1 <= q0 - 4)       bconst = bias0;
        else if (k0 >= q0 + BQ2 - 1 + 4)  bconst = bias8;
        else                               midband = true;

        float vmax1 = -INFINITY, vmax2 = -INFINITY;
        #pragma unroll
        for (int j = 0; j < 8; j++) {
            const int kl = 8*j + cb;
            const uint32_t mw = mbits[(k0 >> 5) + (kl >> 5)];
            const float a0 = ((mw >> (kl & 31)) & 1u)       ? 0.f : -30000.f;
            const float a1 = ((mw >> ((kl & 31) + 1)) & 1u) ? 0.f : -30000.f;
            float b00, b01, b10, b11;
            if (!midband) { b00 = b01 = b10 = b11 = bconst; }
            else {
                int d = k0 + kl - qi1 + 4;
                b00 = sbias[min(max(d,   0), 8)];
                b01 = sbias[min(max(d+1, 0), 8)];
                b10 = sbias[min(max(d-8, 0), 8)];
                b11 = sbias[min(max(d-7, 0), 8)];
            }
            s[j][0] = fmaf(s[j][0], scale, a0 + b00);
            s[j][1] = fmaf(s[j][1], scale, a1 + b01);
            s[j][2] = fmaf(s[j][2], scale, a0 + b10);
            s[j][3] = fmaf(s[j][3], scale, a1 + b11);
            vmax1 = fmaxf(vmax1, fmaxf(s[j][0], s[j][1]));
            vmax2 = fmaxf(vmax2, fmaxf(s[j][2], s[j][3]));
        }
        vmax1 = fmaxf(vmax1, __shfl_xor_sync(0xffffffffu, vmax1, 1));
        vmax1 = fmaxf(vmax1, __shfl_xor_sync(0xffffffffu, vmax1, 2));
        vmax2 = fmaxf(vmax2, __shfl_xor_sync(0xffffffffu, vmax2, 1));
        vmax2 = fmaxf(vmax2, __shfl_xor_sync(0xffffffffu, vmax2, 2));

        const float mn1 = fmaxf(m1, vmax1);
        const float mn2 = fmaxf(m2, vmax2);
        const float al1 = __expf(m1 - mn1);
        const float al2 = __expf(m2 - mn2);
        float sum1 = 0.f, sum2 = 0.f;
        #pragma unroll
        for (int j = 0; j < 8; j++) {
            s[j][0] = __expf(s[j][0] - mn1);
            s[j][1] = __expf(s[j][1] - mn1);
            s[j][2] = __expf(s[j][2] - mn2);
            s[j][3] = __expf(s[j][3] - mn2);
            sum1 += s[j][0] + s[j][1];
            sum2 += s[j][2] + s[j][3];
        }
        sum1 += __shfl_xor_sync(0xffffffffu, sum1, 1);
        sum1 += __shfl_xor_sync(0xffffffffu, sum1, 2);
        sum2 += __shfl_xor_sync(0xffffffffu, sum2, 1);
        sum2 += __shfl_xor_sync(0xffffffffu, sum2, 2);
        l1 = l1*al1 + sum1;  m1 = mn1;
        l2 = l2*al2 + sum2;  m2 = mn2;

        #pragma unroll
        for (int j = 0; j < 8; j++) {
            o[j][0] *= al1; o[j][1] *= al1;
            o[j][2] *= al2; o[j][3] *= al2;
        }

        // ---- O += P V  (V natural layout, trans ldmatrix)
        #pragma unroll
        for (int kc = 0; kc < 4; kc++) {
            uint32_t Ph[4], Pl[4];
            split2(s[2*kc][0],   s[2*kc][1],   Ph[0], Pl[0]);
            split2(s[2*kc][2],   s[2*kc][3],   Ph[1], Pl[1]);
            split2(s[2*kc+1][0], s[2*kc+1][1], Ph[2], Pl[2]);
            split2(s[2*kc+1][2], s[2*kc+1][3], Ph[3], Pl[3]);
            #pragma unroll
            for (int jp = 0; jp < 4; jp++) {
                uint32_t Bh[4], Bl[4];
                const uint32_t ab = sb + kb + 18432
                                  + (uint32_t)(kc*16)*STRD + vRow + jp*32;
                ldsm_x4_t(Bh[0],Bh[1],Bh[2],Bh[3], ab);
                ldsm_x4_t(Bl[0],Bl[1],Bl[2],Bl[3], ab + 9216);
                mma16816(o[2*jp],   Ph, Bh[0], Bh[1]);
                mma16816(o[2*jp],   Ph, Bl[0], Bl[1]);
                mma16816(o[2*jp],   Pl, Bh[0], Bh[1]);
                mma16816(o[2*jp+1], Ph, Bh[2], Bh[3]);
                mma16816(o[2*jp+1], Ph, Bl[2], Bl[3]);
                mma16816(o[2*jp+1], Pl, Bh[2], Bh[3]);
            }
        }

        __syncthreads();
        if (kt + 2 < NT) ISSUE_KV(kt + 2, kt & 1);
    }

    // ---- epilogue: divide by l, split to bf16 hi/lo hidden
    const float inv1 = 1.f / l1, inv2 = 1.f / l2;
    const size_t o1 = ((size_t)(b*TT + qi1)*HH + h*HD + cb) >> 1;
    const size_t o2 = o1 + (size_t)8*HH/2;
    #pragma unroll
    for (int j = 0; j < 8; j++) {
        uint32_t hh, ll;
        split2(o[j][0]*inv1, o[j][1]*inv1, hh, ll);
        Hhi[o1 + 4*j] = hh; Hlo[o1 + 4*j] = ll;
        split2(o[j][2]*inv2, o[j][3]*inv2, hh, ll);
        Hhi[o2 + 4*j] = hh; Hlo[o2 + 4*j] = ll;
    }
    #undef ISSUE_KV
}

// ---------------------------------------------------------------------------
extern "C" void kernel_launch(void* const* d_in, const int* in_sizes, int n_in,
                              void* d_out, int out_size)
{
    const float* x         = (const float*)d_in[0];
    const int*   text_mask = (const int*)  d_in[1];
    const float* Wq        = (const float*)d_in[2];
    const float* bq        = (const float*)d_in[3];
    const float* Wk        = (const float*)d_in[4];
    const float* bk        = (const float*)d_in[5];
    const float* Wv        = (const float*)d_in[6];
    const float* bv        = (const float*)d_in[7];
    const float* Wo        = (const float*)d_in[8];
    const float* bo        = (const float*)d_in[9];
    const float* rel_bias  = (const float*)d_in[10];
    float* out = (float*)d_out;

    uint32_t *xhi,*xlo,*Qh,*Ql,*Kh,*Kl,*Vh,*Vl,*Hh,*Hl;
    uint32_t *wqh,*wql,*wkh,*wkl,*wvh,*wvl,*woh,*wol;
    cudaGetSymbolAddress((void**)&xhi, g_xhi);  cudaGetSymbolAddress((void**)&xlo, g_xlo);
    cudaGetSymbolAddress((void**)&Qh,  g_Qhi);  cudaGetSymbolAddress((void**)&Ql,  g_Qlo);
    cudaGetSymbolAddress((void**)&Kh,  g_Khi);  cudaGetSymbolAddress((void**)&Kl,  g_Klo);
    cudaGetSymbolAddress((void**)&Vh,  g_Vhi);  cudaGetSymbolAddress((void**)&Vl,  g_Vlo);
    cudaGetSymbolAddress((void**)&Hh,  g_Hhi);  cudaGetSymbolAddress((void**)&Hl,  g_Hlo);
    cudaGetSymbolAddress((void**)&wqh, g_Wqhi); cudaGetSymbolAddress((void**)&wql, g_Wqlo);
    cudaGetSymbolAddress((void**)&wkh, g_Wkhi); cudaGetSymbolAddress((void**)&wkl, g_Wklo);
    cudaGetSymbolAddress((void**)&wvh, g_Wvhi); cudaGetSymbolAddress((void**)&wvl, g_Wvlo);
    cudaGetSymbolAddress((void**)&woh, g_Wohi); cudaGetSymbolAddress((void**)&wol, g_Wolo);

    cudaFuncSetAttribute(gemm_bf16_kernel, cudaFuncAttributeMaxDynamicSharedMemorySize, GEMM_SMEM);
    cudaFuncSetAttribute(attn_bf16_kernel, cudaFuncAttributeMaxDynamicSharedMemorySize, ATT_SMEM);

    // pre-split inputs
    const int nx2 = NTOK*HH/2, nw2 = HH*HH/2;
    split_kernel<<<nx2/256, 256>>>(x,  xhi, xlo, nx2);
    split_kernel<<<nw2/256, 256>>>(Wq, wqh, wql, nw2);
    split_kernel<<<nw2/256, 256>>>(Wk, wkh, wkl, nw2);
    split_kernel<<<nw2/256, 256>>>(Wv, wvh, wvl, nw2);
    split_kernel<<<nw2/256, 256>>>(Wo, woh, wol, nw2);

    const int M = NTOK;
    dim3 gdim(HH/128, M/128);

    gemm_bf16_kernel<<<gdim, 256, GEMM_SMEM>>>(xhi, xlo, wqh, wql, bq, nullptr, Qh, Ql, nullptr, HH);
    gemm_bf16_kernel<<<gdim, 256, GEMM_SMEM>>>(xhi, xlo, wkh, wkl, bk, nullptr, Kh, Kl, nullptr, HH);
    gemm_bf16_kernel<<<gdim, 256, GEMM_SMEM>>>(xhi, xlo, wvh, wvl, bv, nullptr, Vh, Vl, nullptr, HH);

    attn_bf16_kernel<<<dim3(TT/BQ2, NH, BB), 256, ATT_SMEM>>>(
        Qh, Ql, Kh, Kl, Vh, Vl, text_mask, rel_bias, Hh, Hl);

    gemm_bf16_kernel<<<gdim, 256, GEMM_SMEM>>>(Hh, Hl, woh, wol, bo, out, nullptr, nullptr, text_mask, HH);
}

// round 8
// speedup vs baseline: 2.9340x; 1.0104x over previous
#include <cuda_runtime.h>
#include <cuda_bf16.h>
#include <math.h>
#include <stdint.h>

#define BB 2
#define TT 2048
#define HH 1024
#define NH 16
#define HD 64
#define MAXREL 4

// ---- bf16 hi/lo scratch (uint32 = bf16x2), static device globals ----
#define NTOK (BB*TT)
__device__ uint32_t g_xhi[NTOK*HH/2],  g_xlo[NTOK*HH/2];
__device__ uint32_t g_Qhi[NTOK*HH/2],  g_Qlo[NTOK*HH/2];
__device__ uint32_t g_Khi[NTOK*HH/2],  g_Klo[NTOK*HH/2];
__device__ uint32_t g_Vhi[NTOK*HH/2],  g_Vlo[NTOK*HH/2];
__device__ uint32_t g_Hhi[NTOK*HH/2],  g_Hlo[NTOK*HH/2];
__device__ uint32_t g_Wqhi[HH*HH/2], g_Wqlo[HH*HH/2];
__device__ uint32_t g_Wkhi[HH*HH/2], g_Wklo[HH*HH/2];
__device__ uint32_t g_Wvhi[HH*HH/2], g_Wvlo[HH*HH/2];
__device__ uint32_t g_Wohi[HH*HH/2], g_Wolo[HH*HH/2];

// ===========================================================================
// Helpers (portable PTX only)
// ===========================================================================
__device__ __forceinline__ uint32_t smem_u32(const void* p) {
    uint32_t a;
    asm("{ .reg .u64 t; cvta.to.shared.u64 t, %1; cvt.u32.u64 %0, t; }" : "=r"(a) : "l"(p));
    return a;
}
__device__ __forceinline__ void ldsm_x4(uint32_t& r0, uint32_t& r1, uint32_t& r2, uint32_t& r3,
                                        uint32_t addr) {
    asm volatile("ldmatrix.sync.aligned.m8n8.x4.shared.b16 {%0,%1,%2,%3}, [%4];"
                 : "=r"(r0), "=r"(r1), "=r"(r2), "=r"(r3) : "r"(addr));
}
__device__ __forceinline__ void ldsm_x4_t(uint32_t& r0, uint32_t& r1, uint32_t& r2, uint32_t& r3,
                                          uint32_t addr) {
    asm volatile("ldmatrix.sync.aligned.m8n8.x4.trans.shared.b16 {%0,%1,%2,%3}, [%4];"
                 : "=r"(r0), "=r"(r1), "=r"(r2), "=r"(r3) : "r"(addr));
}
__device__ __forceinline__ void mma16816(float* c, const uint32_t* a, uint32_t b0, uint32_t b1) {
    asm volatile(
        "mma.sync.aligned.m16n8k16.row.col.f32.bf16.bf16.f32 "
        "{%0,%1,%2,%3}, {%4,%5,%6,%7}, {%8,%9}, {%0,%1,%2,%3};"
        : "+f"(c[0]), "+f"(c[1]), "+f"(c[2]), "+f"(c[3])
        : "r"(a[0]), "r"(a[1]), "r"(a[2]), "r"(a[3]), "r"(b0), "r"(b1));
}
__device__ __forceinline__ void split2(float x, float y, uint32_t& hi, uint32_t& lo) {
    float hx = __bfloat162float(__float2bfloat16(x));
    float hy = __bfloat162float(__float2bfloat16(y));
    asm("cvt.rn.bf16x2.f32 %0, %1, %2;" : "=r"(hi) : "f"(hy), "f"(hx));
    asm("cvt.rn.bf16x2.f32 %0, %1, %2;" : "=r"(lo) : "f"(y - hy), "f"(x - hx));
}
__device__ __forceinline__ void cp_async16(uint32_t d, const void* g) {
    asm volatile("cp.async.cg.shared.global [%0], [%1], 16;" :: "r"(d), "l"(g));
}
__device__ __forceinline__ void cp_commit() {
    asm volatile("cp.async.commit_group;" ::: "memory");
}
template<int W> __device__ __forceinline__ void cp_wait() {
    asm volatile("cp.async.wait_group %0;" :: "n"(W) : "memory");
}

// ===========================================================================
// fp32 -> bf16 hi/lo split (pre-pass, same as proven R5)
// ===========================================================================
__global__ void split_kernel(const float* __restrict__ src,
                             uint32_t* __restrict__ hi, uint32_t* __restrict__ lo, int n2)
{
    int i = blockIdx.x * blockDim.x + threadIdx.x;
    if (i < n2) {
        float2 v = ((const float2*)src)[i];
        uint32_t h, l;
        split2(v.x, v.y, h, l);
        hi[i] = h; lo[i] = l;
    }
}

// ===========================================================================
// bf16 hi/lo GEMM (proven R5, unchanged)
// ===========================================================================
#define GK 1024
#define KC 32
#define NCHUNK (GK / KC)
#define GROWB 80
#define GTILE (128 * GROWB)
#define GBUF  (4 * GTILE)
#define GEMM_SMEM (2 * GBUF)

__global__ __launch_bounds__(256, 2) void gemm_bf16_kernel(
    const uint32_t* __restrict__ Ahi, const uint32_t* __restrict__ Alo,
    const uint32_t* __restrict__ Whi, const uint32_t* __restrict__ Wlo,
    const float* __restrict__ bias,
    float* __restrict__ Cf, uint32_t* __restrict__ Chi, uint32_t* __restrict__ Clo,
    const int* __restrict__ mask, int N)
{
    extern __shared__ char smemraw[];
    const uint32_t sbase = smem_u32(smemraw);

    const int tid  = threadIdx.x;
    const int lane = tid & 31;
    const int wid  = tid >> 5;
    const int wm   = wid & 3;
    const int wn   = wid >> 2;
    const int mbase = blockIdx.y * 128;
    const int nbase = blockIdx.x * 128;

    const int lr = tid >> 1, half = tid & 1;
    const uint32_t* gAh = Ahi + ((size_t)(mbase + lr) << 9) + half * 8;
    const uint32_t* gAl = Alo + ((size_t)(mbase + lr) << 9) + half * 8;
    const uint32_t* gWh = Whi + ((size_t)(nbase + lr) << 9) + half * 8;
    const uint32_t* gWl = Wlo + ((size_t)(nbase + lr) << 9) + half * 8;
    const uint32_t sdst = sbase + lr * GROWB + half * 32;

    float acc[2][8][4];
    #pragma unroll
    for (int mi = 0; mi < 2; mi++)
        #pragma unroll
        for (int j = 0; j < 8; j++)
            #pragma unroll
            for (int e = 0; e < 4; e++) acc[mi][j][e] = 0.f;

    const uint32_t aA = sbase + (uint32_t)(wm*32 + (lane & 15)) * GROWB + ((lane >> 4) * 16);
    const uint32_t aB = sbase + 2*GTILE
                      + (uint32_t)(wn*64 + ((lane >> 4) << 3) + (lane & 7)) * GROWB
                      + (((lane >> 3) & 1) * 16);

    {
        cp_async16(sdst,               gAh); cp_async16(sdst + 16,           gAh + 4);
        cp_async16(sdst + GTILE,       gAl); cp_async16(sdst + GTILE + 16,   gAl + 4);
        cp_async16(sdst + 2*GTILE,     gWh); cp_async16(sdst + 2*GTILE + 16, gWh + 4);
        cp_async16(sdst + 3*GTILE,     gWl); cp_async16(sdst + 3*GTILE + 16, gWl + 4);
        cp_commit();
    }

    for (int c = 0; c < NCHUNK; c++) {
        if (c + 1 < NCHUNK) {
            const uint32_t d = sdst + (uint32_t)((c + 1) & 1) * GBUF;
            const int off = (c + 1) * 16;
            cp_async16(d,               gAh + off); cp_async16(d + 16,           gAh + off + 4);
            cp_async16(d + GTILE,       gAl + off); cp_async16(d + GTILE + 16,   gAl + off + 4);
            cp_async16(d + 2*GTILE,     gWh + off); cp_async16(d + 2*GTILE + 16, gWh + off + 4);
            cp_async16(d + 3*GTILE,     gWl + off); cp_async16(d + 3*GTILE + 16, gWl + off + 4);
            cp_commit();
            cp_wait<1>();
        } else {
            cp_wait<0>();
        }
        __syncthreads();

        const uint32_t boff = (uint32_t)(c & 1) * GBUF;
        #pragma unroll
        for (int ks = 0; ks < 2; ks++) {
            uint32_t Ah[2][4], Al[2][4];
            ldsm_x4(Ah[0][0],Ah[0][1],Ah[0][2],Ah[0][3], aA + boff + ks*32);
            ldsm_x4(Ah[1][0],Ah[1][1],Ah[1][2],Ah[1][3], aA + boff + 16*GROWB + ks*32);
            ldsm_x4(Al[0][0],Al[0][1],Al[0][2],Al[0][3], aA + boff + GTILE + ks*32);
            ldsm_x4(Al[1][0],Al[1][1],Al[1][2],Al[1][3], aA + boff + GTILE + 16*GROWB + ks*32);
            #pragma unroll
            for (int jp = 0; jp < 4; jp++) {
                uint32_t Bh[4], Bl[4];
                ldsm_x4(Bh[0],Bh[1],Bh[2],Bh[3], aB + boff + jp*16*GROWB + ks*32);
                ldsm_x4(Bl[0],Bl[1],Bl[2],Bl[3], aB + boff + GTILE + jp*16*GROWB + ks*32);
                #pragma unroll
                for (int mi = 0; mi < 2; mi++) {
                    mma16816(acc[mi][2*jp],   Ah[mi], Bh[0], Bh[1]);
                    mma16816(acc[mi][2*jp],   Ah[mi], Bl[0], Bl[1]);
                    mma16816(acc[mi][2*jp],   Al[mi], Bh[0], Bh[1]);
                    mma16816(acc[mi][2*jp+1], Ah[mi], Bh[2], Bh[3]);
                    mma16816(acc[mi][2*jp+1], Ah[mi], Bl[2], Bl[3]);
                    mma16816(acc[mi][2*jp+1], Al[mi], Bh[2], Bh[3]);
                }
            }
        }
        __syncthreads();
    }

    #pragma unroll
    for (int mi = 0; mi < 2; mi++) {
        const int r0 = mbase + wm*32 + mi*16 + (lane >> 2);
        #pragma unroll
        for (int j = 0; j < 8; j++) {
            const int col = nbase + wn*64 + j*8 + (lane & 3)*2;
            const float b0 = bias[col], b1 = bias[col+1];
            float c0 = acc[mi][j][0] + b0, c1 = acc[mi][j][1] + b1;
            float c2 = acc[mi][j][2] + b0, c3 = acc[mi][j][3] + b1;
            if (Cf) {
                const float mv0 = (float)mask[r0];
                const float mv1 = (float)mask[r0 + 8];
                *(float2*)&Cf[(size_t)r0 * N + col]     = make_float2(c0*mv0, c1*mv0);
                *(float2*)&Cf[(size_t)(r0+8) * N + col] = make_float2(c2*mv1, c3*mv1);
            } else {
                uint32_t h, l;
                split2(c0, c1, h, l);
                Chi[((size_t)r0 * N + col) >> 1] = h;
                Clo[((size_t)r0 * N + col) >> 1] = l;
                split2(c2, c3, h, l);
                Chi[((size_t)(r0+8) * N + col) >> 1] = h;
                Clo[((size_t)(r0+8) * N + col) >> 1] = l;
            }
        }
    }
}

// ===========================================================================
// bf16 flash attention, m32 warp tile (R7 with the Q-load defect fixed:
// each thread now copies the FULL 128B hi row + 128B lo row).
// ===========================================================================
#define BQ2 256
#define BK2 64
#define NT  (TT / BK2)
#define STRD 144
#define A_QLO 36864            // Q hi: 256*144 = 36864
#define A_KV  73728            // + buf*36864 ; Khi | Klo(+9216) | Vhi(+18432) | Vlo(+27648)
#define KVBUF 36864
#define A_MB  147456           // 64 uint32 mask bits
#define ATT_SMEM (A_MB + 256)
#define NEGBIG -1.0e30f

__global__ __launch_bounds__(256, 1) void attn_bf16_kernel(
    const uint32_t* __restrict__ Qhi, const uint32_t* __restrict__ Qlo,
    const uint32_t* __restrict__ Khi, const uint32_t* __restrict__ Klo,
    const uint32_t* __restrict__ Vhi, const uint32_t* __restrict__ Vlo,
    const int* __restrict__ mask, const float* __restrict__ rel_bias,
    uint32_t* __restrict__ Hhi, uint32_t* __restrict__ Hlo)
{
    extern __shared__ char sm[];
    const uint32_t sb = smem_u32(sm);
    uint32_t* mbits = (uint32_t*)(sm + A_MB);
    __shared__ float sbias[9];

    const int tid  = threadIdx.x;
    const int lane = tid & 31;
    const int wid  = tid >> 5;
    const int b    = blockIdx.z;
    const int h    = blockIdx.y;
    const int q0   = blockIdx.x * BQ2;
    const float scale = 0.125f;

    if (tid < 9) sbias[tid] = rel_bias[tid*NH + h];

    // mask bitset: 2048 bits = 64 words
    #pragma unroll
    for (int i = 0; i < 8; i++) {
        int v = mask[b*TT + i*256 + tid];
        uint32_t bal = __ballot_sync(0xffffffffu, v != 0);
        if (lane == 0) mbits[i*8 + wid] = bal;
    }

    // Q tile (256 rows, one row per thread) -> SMEM hi/lo.
    // FULL row: 64 bf16 = 32 uint32 = 128 bytes each for hi and lo.
    {
        const int r = tid;
        const size_t g = ((size_t)(b*TT + q0 + r) * HH + h*HD) >> 1;
        const uint32_t d = sb + r*STRD;
        const uint32_t* s0 = Qhi + g;
        const uint32_t* s1 = Qlo + g;
        #pragma unroll
        for (int i = 0; i < 8; i++) {
            cp_async16(d + i*16,         s0 + i*4);
            cp_async16(d + A_QLO + i*16, s1 + i*4);
        }
        cp_commit();
    }

    // K/V tile issue
    const int kvr = tid >> 2, kvq = tid & 3;
    const size_t kvg0 = ((size_t)(b*TT + kvr) * HH + h*HD) >> 1;
    const uint32_t kvd0 = sb + A_KV + kvr*STRD + kvq*32;

    #define ISSUE_KV(KT, BUF) do {                                                  \
        const size_t g_ = kvg0 + (size_t)(KT) * (64*HH/2) + kvq*8;                  \
        const uint32_t d_ = kvd0 + (uint32_t)(BUF) * KVBUF;                         \
        cp_async16(d_,          Khi + g_); cp_async16(d_+16,       Khi + g_ + 4);   \
        cp_async16(d_+9216,     Klo + g_); cp_async16(d_+9216+16,  Klo + g_ + 4);   \
        cp_async16(d_+18432,    Vhi + g_); cp_async16(d_+18432+16, Vhi + g_ + 4);   \
        cp_async16(d_+27648,    Vlo + g_); cp_async16(d_+27648+16, Vlo + g_ + 4);   \
        cp_commit();                                                                \
    } while (0)

    ISSUE_KV(0, 0);
    ISSUE_KV(1, 1);
    cp_wait<2>();        // Q ready
    __syncthreads();

    const uint32_t aQ   = sb + (uint32_t)(wid*32 + (lane & 15))*STRD + (lane >> 4)*16;
    const uint32_t bRow = (uint32_t)(((lane >> 4) << 3) + (lane & 7))*STRD
                        + ((lane >> 3) & 1)*16;                       // K non-trans
    const uint32_t vRow = (uint32_t)((((lane >> 3) & 1) << 3) + (lane & 7))*STRD
                        + (lane >> 4)*16;                             // V trans

    const int cb = (lane & 3) * 2;
    const int r1 = lane >> 2;
    const int qbase = q0 + wid*32 + r1;           // + mi*16
    const float bias0 = sbias[0], bias8 = sbias[8];

    float o[2][8][4];
    #pragma unroll
    for (int mi = 0; mi < 2; mi++)
        #pragma unroll
        for (int j = 0; j < 8; j++)
            #pragma unroll
            for (int e = 0; e < 4; e++) o[mi][j][e] = 0.f;
    float mA[2] = {NEGBIG, NEGBIG}, mB[2] = {NEGBIG, NEGBIG};
    float lA[2] = {0.f, 0.f},       lB[2] = {0.f, 0.f};

    for (int kt = 0; kt < NT; kt++) {
        const int k0 = kt * BK2;
        const uint32_t kb = A_KV + (uint32_t)(kt & 1) * KVBUF;

        if (kt + 1 < NT) cp_wait<1>(); else cp_wait<0>();
        __syncthreads();

        // ---- S = Q K^T (3-MMA hi/lo), m32 per warp
        float s[2][8][4];
        #pragma unroll
        for (int mi = 0; mi < 2; mi++)
            #pragma unroll
            for (int j = 0; j < 8; j++)
                #pragma unroll
                for (int e = 0; e < 4; e++) s[mi][j][e] = 0.f;

        #pragma unroll
        for (int ks = 0; ks < 4; ks++) {
            uint32_t qh[2][4], ql[2][4];
            ldsm_x4(qh[0][0], qh[0][1], qh[0][2], qh[0][3], aQ + ks*32);
            ldsm_x4(qh[1][0], qh[1][1], qh[1][2], qh[1][3], aQ + 16*STRD + ks*32);
            ldsm_x4(ql[0][0], ql[0][1], ql[0][2], ql[0][3], aQ + A_QLO + ks*32);
            ldsm_x4(ql[1][0], ql[1][1], ql[1][2], ql[1][3], aQ + A_QLO + 16*STRD + ks*32);
            #pragma unroll
            for (int jp = 0; jp < 4; jp++) {
                uint32_t Bh[4], Bl[4];
                const uint32_t ab = sb + kb + (uint32_t)(jp*16)*STRD + bRow + ks*32;
                ldsm_x4(Bh[0],Bh[1],Bh[2],Bh[3], ab);
                ldsm_x4(Bl[0],Bl[1],Bl[2],Bl[3], ab + 9216);
                #pragma unroll
                for (int mi = 0; mi < 2; mi++) {
                    mma16816(s[mi][2*jp],   qh[mi], Bh[0], Bh[1]);
                    mma16816(s[mi][2*jp],   qh[mi], Bl[0], Bl[1]);
                    mma16816(s[mi][2*jp],   ql[mi], Bh[0], Bh[1]);
                    mma16816(s[mi][2*jp+1], qh[mi], Bh[2], Bh[3]);
                    mma16816(s[mi][2*jp+1], qh[mi], Bl[2], Bl[3]);
                    mma16816(s[mi][2*jp+1], ql[mi], Bh[2], Bh[3]);
                }
            }
        }

        // ---- scale + rel-bias + mask + online softmax (expf, R5 constants)
        float bconst = 0.f;
        bool midband = false;
        if (k0 + BK2 - 1 <= q0 - 4)       bconst = bias0;
        else if (k0 >= q0 + BQ2 - 1 + 4)  bconst = bias8;
        else                               midband = true;

        #pragma unroll
        for (int mi = 0; mi < 2; mi++) {
            const int qi = qbase + mi*16;
            float vmax1 = NEGBIG, vmax2 = NEGBIG;
            #pragma unroll
            for (int j = 0; j < 8; j++) {
                const int kl = 8*j + cb;
                const uint32_t mw = mbits[(k0 >> 5) + (kl >> 5)];
                const float a0 = ((mw >> (kl & 31)) & 1u)       ? 0.f : -30000.f;
                const float a1 = ((mw >> ((kl & 31) + 1)) & 1u) ? 0.f : -30000.f;
                float b00, b01, b10, b11;
                if (!midband) { b00 = b01 = b10 = b11 = bconst; }
                else {
                    int d = k0 + kl - qi + 4;
                    b00 = sbias[min(max(d,   0), 8)];
                    b01 = sbias[min(max(d+1, 0), 8)];
                    b10 = sbias[min(max(d-8, 0), 8)];
                    b11 = sbias[min(max(d-7, 0), 8)];
                }
                s[mi][j][0] = fmaf(s[mi][j][0], scale, a0 + b00);
                s[mi][j][1] = fmaf(s[mi][j][1], scale, a1 + b01);
                s[mi][j][2] = fmaf(s[mi][j][2], scale, a0 + b10);
                s[mi][j][3] = fmaf(s[mi][j][3], scale, a1 + b11);
                vmax1 = fmaxf(vmax1, fmaxf(s[mi][j][0], s[mi][j][1]));
                vmax2 = fmaxf(vmax2, fmaxf(s[mi][j][2], s[mi][j][3]));
            }
            vmax1 = fmaxf(vmax1, __shfl_xor_sync(0xffffffffu, vmax1, 1));
            vmax1 = fmaxf(vmax1, __shfl_xor_sync(0xffffffffu, vmax1, 2));
            vmax2 = fmaxf(vmax2, __shfl_xor_sync(0xffffffffu, vmax2, 1));
            vmax2 = fmaxf(vmax2, __shfl_xor_sync(0xffffffffu, vmax2, 2));

            const float mn1 = fmaxf(mA[mi], vmax1);
            const float mn2 = fmaxf(mB[mi], vmax2);
            const float al1 = __expf(mA[mi] - mn1);
            const float al2 = __expf(mB[mi] - mn2);
            float sum1 = 0.f, sum2 = 0.f;
            #pragma unroll
            for (int j = 0; j < 8; j++) {
                s[mi][j][0] = __expf(s[mi][j][0] - mn1);
                s[mi][j][1] = __expf(s[mi][j][1] - mn1);
                s[mi][j][2] = __expf(s[mi][j][2] - mn2);
                s[mi][j][3] = __expf(s[mi][j][3] - mn2);
                sum1 += s[mi][j][0] + s[mi][j][1];
                sum2 += s[mi][j][2] + s[mi][j][3];
            }
            sum1 += __shfl_xor_sync(0xffffffffu, sum1, 1);
            sum1 += __shfl_xor_sync(0xffffffffu, sum1, 2);
            sum2 += __shfl_xor_sync(0xffffffffu, sum2, 1);
            sum2 += __shfl_xor_sync(0xffffffffu, sum2, 2);
            lA[mi] = lA[mi]*al1 + sum1;  mA[mi] = mn1;
            lB[mi] = lB[mi]*al2 + sum2;  mB[mi] = mn2;

            #pragma unroll
            for (int j = 0; j < 8; j++) {
                o[mi][j][0] *= al1; o[mi][j][1] *= al1;
                o[mi][j][2] *= al2; o[mi][j][3] *= al2;
            }
        }

        // ---- O += P V (3-MMA hi/lo); V natural layout, trans ldmatrix
        #pragma unroll
        for (int kc = 0; kc < 4; kc++) {
            uint32_t Ph[2][4], Pl[2][4];
            #pragma unroll
            for (int mi = 0; mi < 2; mi++) {
                split2(s[mi][2*kc][0],   s[mi][2*kc][1],   Ph[mi][0], Pl[mi][0]);
                split2(s[mi][2*kc][2],   s[mi][2*kc][3],   Ph[mi][1], Pl[mi][1]);
                split2(s[mi][2*kc+1][0], s[mi][2*kc+1][1], Ph[mi][2], Pl[mi][2]);
                split2(s[mi][2*kc+1][2], s[mi][2*kc+1][3], Ph[mi][3], Pl[mi][3]);
            }
            #pragma unroll
            for (int jp = 0; jp < 4; jp++) {
                uint32_t Bh[4], Bl[4];
                const uint32_t ab = sb + kb + 18432
                                  + (uint32_t)(kc*16)*STRD + vRow + jp*32;
                ldsm_x4_t(Bh[0],Bh[1],Bh[2],Bh[3], ab);
                ldsm_x4_t(Bl[0],Bl[1],Bl[2],Bl[3], ab + 9216);
                #pragma unroll
                for (int mi = 0; mi < 2; mi++) {
                    mma16816(o[mi][2*jp],   Ph[mi], Bh[0], Bh[1]);
                    mma16816(o[mi][2*jp],   Ph[mi], Bl[0], Bl[1]);
                    mma16816(o[mi][2*jp],   Pl[mi], Bh[0], Bh[1]);
                    mma16816(o[mi][2*jp+1], Ph[mi], Bh[2], Bh[3]);
                    mma16816(o[mi][2*jp+1], Ph[mi], Bl[2], Bl[3]);
                    mma16816(o[mi][2*jp+1], Pl[mi], Bh[2], Bh[3]);
                }
            }
        }

        __syncthreads();
        if (kt + 2 < NT) ISSUE_KV(kt + 2, kt & 1);
    }

    // ---- epilogue: divide by l, split to bf16 hi/lo hidden
    #pragma unroll
    for (int mi = 0; mi < 2; mi++) {
        const float inv1 = 1.f / lA[mi], inv2 = 1.f / lB[mi];
        const int qi = qbase + mi*16;
        const size_t o1 = ((size_t)(b*TT + qi)*HH + h*HD + cb) >> 1;
        const size_t o2 = o1 + (size_t)8*HH/2;
        #pragma unroll
        for (int j = 0; j < 8; j++) {
            uint32_t hh, ll;
            split2(o[mi][j][0]*inv1, o[mi][j][1]*inv1, hh, ll);
            Hhi[o1 + 4*j] = hh; Hlo[o1 + 4*j] = ll;
            split2(o[mi][j][2]*inv2, o[mi][j][3]*inv2, hh, ll);
            Hhi[o2 + 4*j] = hh; Hlo[o2 + 4*j] = ll;
        }
    }
    #undef ISSUE_KV
}

// ---------------------------------------------------------------------------
extern "C" void kernel_launch(void* const* d_in, const int* in_sizes, int n_in,
                              void* d_out, int out_size)
{
    const float* x         = (const float*)d_in[0];
    const int*   text_mask = (const int*)  d_in[1];
    const float* Wq        = (const float*)d_in[2];
    const float* bq        = (const float*)d_in[3];
    const float* Wk        = (const float*)d_in[4];
    const float* bk        = (const float*)d_in[5];
    const float* Wv        = (const float*)d_in[6];
    const float* bv        = (const float*)d_in[7];
    const float* Wo        = (const float*)d_in[8];
    const float* bo        = (const float*)d_in[9];
    const float* rel_bias  = (const float*)d_in[10];
    float* out = (float*)d_out;

    uint32_t *xhi,*xlo,*Qh,*Ql,*Kh,*Kl,*Vh,*Vl,*Hh,*Hl;
    uint32_t *wqh,*wql,*wkh,*wkl,*wvh,*wvl,*woh,*wol;
    cudaGetSymbolAddress((void**)&xhi, g_xhi);  cudaGetSymbolAddress((void**)&xlo, g_xlo);
    cudaGetSymbolAddress((void**)&Qh,  g_Qhi);  cudaGetSymbolAddress((void**)&Ql,  g_Qlo);
    cudaGetSymbolAddress((void**)&Kh,  g_Khi);  cudaGetSymbolAddress((void**)&Kl,  g_Klo);
    cudaGetSymbolAddress((void**)&Vh,  g_Vhi);  cudaGetSymbolAddress((void**)&Vl,  g_Vlo);
    cudaGetSymbolAddress((void**)&Hh,  g_Hhi);  cudaGetSymbolAddress((void**)&Hl,  g_Hlo);
    cudaGetSymbolAddress((void**)&wqh, g_Wqhi); cudaGetSymbolAddress((void**)&wql, g_Wqlo);
    cudaGetSymbolAddress((void**)&wkh, g_Wkhi); cudaGetSymbolAddress((void**)&wkl, g_Wklo);
    cudaGetSymbolAddress((void**)&wvh, g_Wvhi); cudaGetSymbolAddress((void**)&wvl, g_Wvlo);
    cudaGetSymbolAddress((void**)&woh, g_Wohi); cudaGetSymbolAddress((void**)&wol, g_Wolo);

    cudaFuncSetAttribute(gemm_bf16_kernel, cudaFuncAttributeMaxDynamicSharedMemorySize, GEMM_SMEM);
    cudaFuncSetAttribute(attn_bf16_kernel, cudaFuncAttributeMaxDynamicSharedMemorySize, ATT_SMEM);

    // pre-split inputs (R5 style: separate launches)
    const int nx2 = NTOK*HH/2, nw2 = HH*HH/2;
    split_kernel<<<nx2/256, 256>>>(x,  xhi, xlo, nx2);
    split_kernel<<<nw2/256, 256>>>(Wq, wqh, wql, nw2);
    split_kernel<<<nw2/256, 256>>>(Wk, wkh, wkl, nw2);
    split_kernel<<<nw2/256, 256>>>(Wv, wvh, wvl, nw2);
    split_kernel<<<nw2/256, 256>>>(Wo, woh, wol, nw2);

    const int M = NTOK;
    dim3 gdim(HH/128, M/128);

    gemm_bf16_kernel<<<gdim, 256, GEMM_SMEM>>>(xhi, xlo, wqh, wql, bq, nullptr, Qh, Ql, nullptr, HH);
    gemm_bf16_kernel<<<gdim, 256, GEMM_SMEM>>>(xhi, xlo, wkh, wkl, bk, nullptr, Kh, Kl, nullptr, HH);
    gemm_bf16_kernel<<<gdim, 256, GEMM_SMEM>>>(xhi, xlo, wvh, wvl, bv, nullptr, Vh, Vl, nullptr, HH);

    attn_bf16_kernel<<<dim3(TT/BQ2, NH, BB), 256, ATT_SMEM>>>(
        Qh, Ql, Kh, Kl, Vh, Vl, text_mask, rel_bias, Hh, Hl);

    gemm_bf16_kernel<<<gdim, 256, GEMM_SMEM>>>(Hh, Hl, woh, wol, bo, out, nullptr, nullptr, text_mask, HH);
}